// round 11
// baseline (speedup 1.0000x reference)
#include <cuda_runtime.h>
#include <cuda_bf16.h>
#include <cstddef>

#define T_STEPS 2048
#define BATCH   64
#define HID     128
#define GATES   512          // 4*HID
#define NSM     148

typedef unsigned long long ull;

// ---- packed fp32x2 helpers (sm_100+) --------------------------------------
__device__ __forceinline__ ull ffma2(ull a, ull b, ull c) {
    ull d;
    asm("fma.rn.f32x2 %0, %1, %2, %3;" : "=l"(d) : "l"(a), "l"(b), "l"(c));
    return d;
}
__device__ __forceinline__ ull pack2(float lo, float hi) {
    ull r; asm("mov.b64 %0, {%1, %2};" : "=l"(r) : "f"(lo), "f"(hi)); return r;
}
__device__ __forceinline__ float2 unpack2(ull v) {
    float2 f; asm("mov.b64 {%0, %1}, %2;" : "=f"(f.x), "=f"(f.y) : "l"(v)); return f;
}

// ---- cluster / DSMEM helpers ----------------------------------------------
__device__ __forceinline__ unsigned cluster_rank() {
    unsigned r; asm("mov.u32 %0, %%cluster_ctarank;" : "=r"(r)); return r;
}
__device__ __forceinline__ unsigned mapa_peer(unsigned local_addr, unsigned peer) {
    unsigned r;
    asm("mapa.shared::cluster.u32 %0, %1, %2;" : "=r"(r) : "r"(local_addr), "r"(peer));
    return r;
}
__device__ __forceinline__ void st_cluster_f32(unsigned addr, float v) {
    asm volatile("st.shared::cluster.f32 [%0], %1;" :: "r"(addr), "f"(v) : "memory");
}
__device__ __forceinline__ void st_release_flag(unsigned addr, unsigned v) {
    asm volatile("st.release.cluster.shared::cluster.u32 [%0], %1;" :: "r"(addr), "r"(v) : "memory");
}
__device__ __forceinline__ unsigned ld_acquire_flag(unsigned addr) {
    unsigned v;
    asm volatile("ld.acquire.cluster.shared::cta.u32 %0, [%1];" : "=r"(v) : "r"(addr) : "memory");
    return v;
}
__device__ __forceinline__ void cluster_sync() {
    asm volatile("barrier.cluster.arrive.aligned;" ::: "memory");
    asm volatile("barrier.cluster.wait.aligned;" ::: "memory");
}

// Scratch (device globals; no allocations allowed)
__device__ float g_gxA[(size_t)BATCH * T_STEPS * GATES];  // 256 MB
__device__ float g_gxB[(size_t)BATCH * T_STEPS * GATES];  // 256 MB
__device__ float g_h  [(size_t)BATCH * T_STEPS * HID];    // 64 MB
__device__ int   g_sync[3 * 2 * BATCH + 2];               // prog[3][128] + 2 tile ctrs

// ---------------------------------------------------------------------------
// GEMM tile machinery (bf16 3-product split, fp32 acc, ldmatrix)
// ---------------------------------------------------------------------------
#define SR 136   // padded bf16 row stride

__device__ __forceinline__ void mma_bf16(float* d, const unsigned* a, const unsigned* b) {
    asm volatile(
        "mma.sync.aligned.m16n8k16.row.col.f32.bf16.bf16.f32 "
        "{%0,%1,%2,%3}, {%4,%5,%6,%7}, {%8,%9}, {%0,%1,%2,%3};"
        : "+f"(d[0]), "+f"(d[1]), "+f"(d[2]), "+f"(d[3])
        : "r"(a[0]), "r"(a[1]), "r"(a[2]), "r"(a[3]), "r"(b[0]), "r"(b[1]));
}
__device__ __forceinline__ void ldsm_x4(unsigned* r, unsigned addr) {
    asm volatile("ldmatrix.sync.aligned.m8n8.x4.shared.b16 {%0,%1,%2,%3}, [%4];"
                 : "=r"(r[0]), "=r"(r[1]), "=r"(r[2]), "=r"(r[3]) : "r"(addr));
}

__device__ void gemm_tile(const float* __restrict__ A, const float* __restrict__ W,
                          const float* __restrict__ bih, const float* __restrict__ bhh,
                          float* __restrict__ out, int brow, int bcol, char* gsm)
{
    __nv_bfloat16* a_hi = (__nv_bfloat16*)gsm;                  // [128][SR]
    __nv_bfloat16* a_lo = a_hi + 128 * SR;
    __nv_bfloat16* w_hi = a_lo + 128 * SR;
    __nv_bfloat16* w_lo = w_hi + 128 * SR;
    float*         bias_s = (float*)(w_lo + 128 * SR);          // [128]

    const int tid = threadIdx.x;
    if (tid < 128) bias_s[tid] = bih[bcol + tid] + bhh[bcol + tid];

    {
        const int row = tid >> 1;
        const int cb  = (tid & 1) * 64;
        const float* Ar = A + (size_t)(brow + row) * HID + cb;
        const float* Wr = W + (size_t)(bcol + row) * HID + cb;
        __nv_bfloat16* ah = a_hi + row * SR + cb;
        __nv_bfloat16* al = a_lo + row * SR + cb;
        __nv_bfloat16* wh = w_hi + row * SR + cb;
        __nv_bfloat16* wl = w_lo + row * SR + cb;
#pragma unroll 4
        for (int c = 0; c < 64; c += 4) {
            float4 v = *(const float4*)(Ar + c);
            __nv_bfloat16 hx = __float2bfloat16_rn(v.x);
            __nv_bfloat16 hy = __float2bfloat16_rn(v.y);
            __nv_bfloat16 hz = __float2bfloat16_rn(v.z);
            __nv_bfloat16 hw = __float2bfloat16_rn(v.w);
            __nv_bfloat162 H0; H0.x = hx; H0.y = hy;
            __nv_bfloat162 H1; H1.x = hz; H1.y = hw;
            __nv_bfloat162 L0 = __floats2bfloat162_rn(v.x - __bfloat162float(hx),
                                                      v.y - __bfloat162float(hy));
            __nv_bfloat162 L1 = __floats2bfloat162_rn(v.z - __bfloat162float(hz),
                                                      v.w - __bfloat162float(hw));
            *(__nv_bfloat162*)(ah + c)     = H0;
            *(__nv_bfloat162*)(ah + c + 2) = H1;
            *(__nv_bfloat162*)(al + c)     = L0;
            *(__nv_bfloat162*)(al + c + 2) = L1;

            float4 u = *(const float4*)(Wr + c);
            __nv_bfloat16 gx = __float2bfloat16_rn(u.x);
            __nv_bfloat16 gy = __float2bfloat16_rn(u.y);
            __nv_bfloat16 gz = __float2bfloat16_rn(u.z);
            __nv_bfloat16 gw = __float2bfloat16_rn(u.w);
            __nv_bfloat162 G0; G0.x = gx; G0.y = gy;
            __nv_bfloat162 G1; G1.x = gz; G1.y = gw;
            __nv_bfloat162 M0 = __floats2bfloat162_rn(u.x - __bfloat162float(gx),
                                                      u.y - __bfloat162float(gy));
            __nv_bfloat162 M1 = __floats2bfloat162_rn(u.z - __bfloat162float(gz),
                                                      u.w - __bfloat162float(gw));
            *(__nv_bfloat162*)(wh + c)     = G0;
            *(__nv_bfloat162*)(wh + c + 2) = G1;
            *(__nv_bfloat162*)(wl + c)     = M0;
            *(__nv_bfloat162*)(wl + c + 2) = M1;
        }
    }
    __syncthreads();

    const int wid    = tid >> 5;
    const int lane   = tid & 31;
    const int warp_m = wid >> 1;
    const int warp_n = wid & 1;
    const int m_base = warp_m * 32;
    const int n_base = warp_n * 64;

    const unsigned a_hi_s = (unsigned)__cvta_generic_to_shared(a_hi);
    const unsigned a_lo_s = (unsigned)__cvta_generic_to_shared(a_lo);
    const unsigned w_hi_s = (unsigned)__cvta_generic_to_shared(w_hi);
    const unsigned w_lo_s = (unsigned)__cvta_generic_to_shared(w_lo);

    const int arow  = m_base + (lane & 15);
    const int akoff = (lane >> 4) * 8;
    const int gsel  = lane >> 3;
    const int brow_ = n_base + ((gsel >> 1) & 1) * 8 + (lane & 7);
    const int bkoff = (gsel & 1) * 8;

    float d[2][8][4];
#pragma unroll
    for (int mi = 0; mi < 2; mi++)
#pragma unroll
        for (int ni = 0; ni < 8; ni++)
#pragma unroll
            for (int e = 0; e < 4; e++) d[mi][ni][e] = 0.f;

#pragma unroll
    for (int k0 = 0; k0 < HID; k0 += 16) {
        unsigned ah[2][4], al[2][4];
#pragma unroll
        for (int mi = 0; mi < 2; mi++) {
            unsigned off = (unsigned)(((arow + mi * 16) * SR + akoff + k0) * 2);
            ldsm_x4(ah[mi], a_hi_s + off);
            ldsm_x4(al[mi], a_lo_s + off);
        }
        unsigned bh[4][4], bl[4][4];
#pragma unroll
        for (int nb = 0; nb < 4; nb++) {
            unsigned off = (unsigned)(((brow_ + nb * 16) * SR + bkoff + k0) * 2);
            ldsm_x4(bh[nb], w_hi_s + off);
            ldsm_x4(bl[nb], w_lo_s + off);
        }
#pragma unroll
        for (int mi = 0; mi < 2; mi++)
#pragma unroll
            for (int nb = 0; nb < 4; nb++) {
                mma_bf16(d[mi][2 * nb],     ah[mi], &bh[nb][0]);
                mma_bf16(d[mi][2 * nb],     ah[mi], &bl[nb][0]);
                mma_bf16(d[mi][2 * nb],     al[mi], &bh[nb][0]);
                mma_bf16(d[mi][2 * nb + 1], ah[mi], &bh[nb][2]);
                mma_bf16(d[mi][2 * nb + 1], ah[mi], &bl[nb][2]);
                mma_bf16(d[mi][2 * nb + 1], al[mi], &bh[nb][2]);
            }
    }

    const int tr = lane >> 2;
    const int tc = (lane & 3) * 2;
#pragma unroll
    for (int mi = 0; mi < 2; mi++) {
        int gr0 = brow + m_base + mi * 16 + tr;
#pragma unroll
        for (int ni = 0; ni < 8; ni++) {
            int lc = n_base + ni * 8 + tc;
            float2 bv = *(const float2*)&bias_s[lc];
            float2 o0 = {d[mi][ni][0] + bv.x, d[mi][ni][1] + bv.y};
            float2 o1 = {d[mi][ni][2] + bv.x, d[mi][ni][3] + bv.y};
            *(float2*)(out + (size_t)gr0 * GATES + bcol + lc)       = o0;
            *(float2*)(out + (size_t)(gr0 + 8) * GATES + bcol + lc) = o1;
        }
    }
}

// Standalone layer-0 GEMM over the whole input
__global__ __launch_bounds__(256) void gemm0_kernel(
    const float* __restrict__ A, const float* __restrict__ W,
    const float* __restrict__ bih, const float* __restrict__ bhh)
{
    extern __shared__ char gsm[];
    gemm_tile(A, W, bih, bhh, g_gxA, blockIdx.x * 128, blockIdx.y * 128, gsm);
}

// ---------------------------------------------------------------------------
// Recurrence: 2-CTA cluster per batch row. Each CTA computes 256 gate rows
// (its j-half of all 4 gates), thread = 1 row, ALL 64 weight pairs in regs.
// h exchanged per step via DSMEM store + release/acquire flag. Own-half
// matvec runs while the peer half is in flight.
// ---------------------------------------------------------------------------
__device__ __forceinline__ float sigm(float x) {
    return __fdividef(1.f, 1.f + __expf(-x));
}
__device__ __forceinline__ float tanh_fast(float x) {
    float e = __expf(2.f * x);
    return 1.f - __fdividef(2.f, e + 1.f);
}

__device__ void rec_body(const float* __restrict__ whh, const float* __restrict__ gx,
                         int* __restrict__ prog, int b, unsigned rank, char* smraw)
{
    float*    h0    = (float*)smraw;             // h buffer, even t
    float*    h1    = h0 + HID;                  // h buffer, odd t
    float*    g_act = h1 + HID;                  // 256 activated gate values
    unsigned* flag  = (unsigned*)(g_act + 256);  // peer-written h counter

    const int tid  = threadIdx.x;
    const int gate = tid >> 6;                   // 0=i 1=f 2=g 3=o
    const int j    = tid & 63;
    const int row  = gate * 128 + (int)rank * 64 + j;
    const int own_lo = (int)rank * 32;           // own-half pair offset in h
    const int oth_lo = 32 - own_lo;

    // All 64 weight pairs in registers, own half first (constant indexing!)
    ull w[64];
    {
        const ull* wp = (const ull*)(whh + (size_t)row * HID);
#pragma unroll
        for (int q = 0; q < 32; q++) { w[q] = wp[own_lo + q]; w[32 + q] = wp[oth_lo + q]; }
    }
    if (tid < HID) { h0[tid] = 0.f; h1[tid] = 0.f; }
    if (tid == 0) *flag = 0;
    float c = 0.f;
    __syncthreads();
    cluster_sync();   // peer smem initialized before any DSMEM traffic

    const unsigned smem_u32 = (unsigned)__cvta_generic_to_shared(smraw);
    const unsigned peer     = rank ^ 1u;
    const unsigned peer_h0  = mapa_peer(smem_u32, peer);
    const unsigned peer_h1  = peer_h0 + HID * 4;
    const unsigned peer_flg = mapa_peer(smem_u32 + (2 * HID + 256) * 4, peer);
    const unsigned my_slot  = (rank * 64 + (unsigned)j) * 4;
    const unsigned flag_u32 = smem_u32 + (2 * HID + 256) * 4;

    const float* gxb = gx  + (size_t)b * T_STEPS * GATES;
    float*       hb  = g_h + (size_t)b * T_STEPS * HID;

    float ngx = __ldg(gxb + row);

    for (int t = 0; t < T_STEPS; t++) {
        const ull* h2   = (const ull*)((t & 1) ? h1 : h0);
        float*     hnxt = (t & 1) ? h0 : h1;
        unsigned peer_hnxt = ((t & 1) ? peer_h0 : peer_h1) + my_slot;

        ull acc_a = pack2(ngx, 0.f), acc_b = 0ULL;
        if (t + 1 < T_STEPS) ngx = __ldg(gxb + (size_t)(t + 1) * GATES + row);

        const ull* hown = h2 + own_lo;
#pragma unroll
        for (int q = 0; q < 32; q += 2) {           // own half (locally ready)
            acc_a = ffma2(hown[q],     w[q],     acc_a);
            acc_b = ffma2(hown[q + 1], w[q + 1], acc_b);
        }
        if (t > 0) {                                 // wait peer's h_t half
            while ((int)ld_acquire_flag(flag_u32) < t) { }
        }
        const ull* hoth = h2 + oth_lo;
#pragma unroll
        for (int q = 0; q < 32; q += 2) {           // peer half
            acc_a = ffma2(hoth[q],     w[32 + q],     acc_a);
            acc_b = ffma2(hoth[q + 1], w[32 + q + 1], acc_b);
        }
        float2 va = unpack2(acc_a), vb = unpack2(acc_b);
        float pre = (va.x + vb.x) + (va.y + vb.y);
        g_act[tid] = (gate == 2) ? tanh_fast(pre) : sigm(pre);
        __syncthreads();                             // g_act ready
        if (tid < 64) {
            float i_ = g_act[tid];
            float f_ = g_act[64 + tid];
            float g_ = g_act[128 + tid];
            float o_ = g_act[192 + tid];
            c = fmaf(f_, c, i_ * g_);
            float hv = o_ * tanh_fast(c);
            hnxt[rank * 64 + tid] = hv;              // local copy
            st_cluster_f32(peer_hnxt, hv);           // peer copy (DSMEM)
            hb[(size_t)t * HID + rank * 64 + tid] = hv;
        }
        __syncthreads();                             // local h ready; orders DSMEM stores
        if (tid == 0) {
            st_release_flag(peer_flg, (unsigned)(t + 1));
            if ((t & 63) == 63) {
                __threadfence();
                atomicExch(prog + 2 * b + (int)rank, t + 1);
            }
        }
    }
    cluster_sync();   // peer's in-flight DSMEM stores land before smem reuse/exit
}

// ---------------------------------------------------------------------------
// GEMM worker: pulls 128x128 tiles from a shared atomic pool, paced by the
// recurrence's per-CTA progress counters. Tiles ordered t-chunk-major.
// ---------------------------------------------------------------------------
__device__ void gemm_worker(const float* __restrict__ W,
                            const float* __restrict__ bih, const float* __restrict__ bhh,
                            float* __restrict__ out, int* __restrict__ prog,
                            int* __restrict__ ctr, char* gsm)
{
    const int tid = threadIdx.x;
    __shared__ int s_idx;
    const int NT = 16 * BATCH * 4;   // 4096 tiles
    while (true) {
        if (tid == 0) s_idx = atomicAdd(ctr, 1);
        __syncthreads();
        int idx = s_idx;
        __syncthreads();
        if (idx >= NT) break;
        int tt  = idx >> 8;
        int rem = idx & 255;
        int b   = rem >> 2;
        int cy  = rem & 3;
        int need = (tt + 1) * 128;
        if (tid == 0) {
            while (true) {
                int v0, v1;
                asm volatile("ld.global.cg.u32 %0, [%1];" : "=r"(v0) : "l"(prog + 2 * b));
                asm volatile("ld.global.cg.u32 %0, [%1];" : "=r"(v1) : "l"(prog + 2 * b + 1));
                if (v0 >= need && v1 >= need) break;
                __nanosleep(256);
            }
            __threadfence();
        }
        __syncthreads();
        gemm_tile(g_h, W, bih, bhh, out, b * T_STEPS + tt * 128, cy * 128, gsm);
        __syncthreads();
    }
}

// ---------------------------------------------------------------------------
// Combined layer kernel (cluster 2): blocks [0,128) = rec clusters (2 per
// batch row); blocks [128,148) = gemm workers. Rec CTAs join the gemm tile
// pool after finishing their row.
// ---------------------------------------------------------------------------
__global__ __launch_bounds__(256, 1) __cluster_dims__(2, 1, 1)
void layer_kernel(
    const float* __restrict__ whh, const float* __restrict__ gx_in,
    const float* __restrict__ wih_next, const float* __restrict__ bih_next,
    const float* __restrict__ bhh_next, float* __restrict__ gx_out,
    int* __restrict__ prog, int* __restrict__ ctr, int do_gemm)
{
    extern __shared__ char smraw[];
    if (blockIdx.x < 2 * BATCH) {
        rec_body(whh, gx_in, prog, blockIdx.x >> 1, cluster_rank(), smraw);
        if (do_gemm)
            gemm_worker(wih_next, bih_next, bhh_next, gx_out, prog, ctr, smraw);
    } else if (do_gemm) {
        gemm_worker(wih_next, bih_next, bhh_next, gx_out, prog, ctr, smraw);
    }
}

// ---------------------------------------------------------------------------
// MLP head: h_last[64,128] -> 64 -> 32 -> 10 (all linear)
// ---------------------------------------------------------------------------
__global__ __launch_bounds__(256) void mlp_kernel(
    const float* __restrict__ w1, const float* __restrict__ b1,
    const float* __restrict__ w2, const float* __restrict__ b2,
    const float* __restrict__ w3, const float* __restrict__ b3,
    float* __restrict__ out)
{
    extern __shared__ float sm[];
    float* hs = sm;          // 64*128, later reused for y2 (64*32)
    float* y1 = sm + 8192;   // 64*64

    const int tid = threadIdx.x;
    for (int idx = tid; idx < 8192; idx += 256) {
        int b = idx >> 7, j = idx & 127;
        hs[idx] = g_h[(size_t)b * T_STEPS * HID + (size_t)(T_STEPS - 1) * HID + j];
    }
    __syncthreads();
    for (int idx = tid; idx < 4096; idx += 256) {
        int b = idx >> 6, o = idx & 63;
        float s = b1[o];
#pragma unroll 8
        for (int k = 0; k < 128; k++) s = fmaf(hs[b * 128 + k], w1[o * 128 + k], s);
        y1[idx] = s;
    }
    __syncthreads();
    for (int idx = tid; idx < 2048; idx += 256) {
        int b = idx >> 5, o = idx & 31;
        float s = b2[o];
#pragma unroll 8
        for (int k = 0; k < 64; k++) s = fmaf(y1[b * 64 + k], w2[o * 64 + k], s);
        hs[idx] = s;  // reuse hs as y2 [64,32]
    }
    __syncthreads();
    for (int idx = tid; idx < 640; idx += 256) {
        int b = idx / 10, o = idx % 10;
        float s = b3[o];
#pragma unroll
        for (int k = 0; k < 32; k++) s = fmaf(hs[b * 32 + k], w3[o * 32 + k], s);
        out[idx] = s;
    }
}

// ---------------------------------------------------------------------------
extern "C" void kernel_launch(void* const* d_in, const int* in_sizes, int n_in,
                              void* d_out, int out_size)
{
    (void)in_sizes; (void)n_in; (void)out_size;
    const float* x   = (const float*)d_in[0];
    const float* wih = (const float*)d_in[1];
    const float* whh = (const float*)d_in[2];
    const float* bih = (const float*)d_in[3];
    const float* bhh = (const float*)d_in[4];
    const float* w1  = (const float*)d_in[5];
    const float* b1  = (const float*)d_in[6];
    const float* w2  = (const float*)d_in[7];
    const float* b2  = (const float*)d_in[8];
    const float* w3  = (const float*)d_in[9];
    const float* b3  = (const float*)d_in[10];

    void *pA = nullptr, *pB = nullptr, *pS = nullptr;
    cudaGetSymbolAddress(&pA, g_gxA);
    cudaGetSymbolAddress(&pB, g_gxB);
    cudaGetSymbolAddress(&pS, g_sync);
    float* bufA = (float*)pA;
    float* bufB = (float*)pB;
    int*   sync = (int*)pS;

    const int GEMM_SMEM = 4 * 128 * SR * 2 + 128 * 4;   // 139,776 B
    const int MLP_SMEM  = (8192 + 4096) * 4;            // 48 KB
    cudaFuncSetAttribute(gemm0_kernel, cudaFuncAttributeMaxDynamicSharedMemorySize, GEMM_SMEM);
    cudaFuncSetAttribute(layer_kernel, cudaFuncAttributeMaxDynamicSharedMemorySize, GEMM_SMEM);
    cudaFuncSetAttribute(mlp_kernel,   cudaFuncAttributeMaxDynamicSharedMemorySize, MLP_SMEM);

    cudaMemsetAsync(sync, 0, (3 * 2 * BATCH + 2) * sizeof(int));

    const size_t WSZ = (size_t)GATES * HID;
    int* prog0 = sync;                 // [128] per layer
    int* prog1 = sync + 2 * BATCH;
    int* prog2 = sync + 4 * BATCH;
    int* ctr0  = sync + 6 * BATCH;     // gemm(1) tile pool
    int* ctr1  = sync + 6 * BATCH + 1; // gemm(2) tile pool

    // Layer 0 input GEMM (from x) -> bufA
    gemm0_kernel<<<dim3(BATCH * T_STEPS / 128, 4), 256, GEMM_SMEM>>>(
        x, wih, bih, bhh);

    // K0: rec(0) on bufA (128 cluster CTAs)  +  gemm(1) -> bufB
    layer_kernel<<<NSM, 256, GEMM_SMEM>>>(
        whh, bufA, wih + WSZ, bih + GATES, bhh + GATES, bufB, prog0, ctr0, 1);
    // K1: rec(1) on bufB  +  gemm(2) -> bufA
    layer_kernel<<<NSM, 256, GEMM_SMEM>>>(
        whh + WSZ, bufB, wih + 2 * WSZ, bih + 2 * GATES, bhh + 2 * GATES, bufA,
        prog1, ctr1, 1);
    // K2: rec(2) on bufA (no gemm)
    layer_kernel<<<2 * BATCH, 256, GEMM_SMEM>>>(
        whh + 2 * WSZ, bufA, nullptr, nullptr, nullptr, nullptr,
        prog2, nullptr, 0);

    mlp_kernel<<<1, 256, MLP_SMEM>>>(w1, b1, w2, b2, w3, b3, (float*)d_out);
}

// round 12
// speedup vs baseline: 1.3303x; 1.3303x over previous
#include <cuda_runtime.h>
#include <cuda_bf16.h>
#include <cstddef>

#define T_STEPS 2048
#define BATCH   64
#define HID     128
#define GATES   512          // 4*HID
#define RK      96           // k-values in registers (as pairs)
#define RKP     (RK/2)       // 48 register pairs
#define SK      (HID - RK)   // 32 k-values in smem
#define SKP     (SK/2)       // 16 smem pairs
#define NSM     148
#define NCHUNK  16           // 2048 / 128
#define CHSTEP  128

typedef unsigned long long ull;

// ---- packed fp32x2 helpers (sm_100+) --------------------------------------
__device__ __forceinline__ ull ffma2(ull a, ull b, ull c) {
    ull d;
    asm("fma.rn.f32x2 %0, %1, %2, %3;" : "=l"(d) : "l"(a), "l"(b), "l"(c));
    return d;
}
__device__ __forceinline__ ull pack2(float lo, float hi) {
    ull r; asm("mov.b64 %0, {%1, %2};" : "=l"(r) : "f"(lo), "f"(hi)); return r;
}
__device__ __forceinline__ float2 unpack2(ull v) {
    float2 f; asm("mov.b64 {%0, %1}, %2;" : "=f"(f.x), "=f"(f.y) : "l"(v)); return f;
}
__device__ __forceinline__ int ld_acquire_gpu(const int* p) {
    int v;
    asm volatile("ld.acquire.gpu.global.s32 %0, [%1];" : "=r"(v) : "l"(p) : "memory");
    return v;
}

// Scratch (device globals; no allocations allowed)
__device__ float g_gxA[(size_t)BATCH * T_STEPS * GATES];  // gx0, then reused for gx2
__device__ float g_gxB[(size_t)BATCH * T_STEPS * GATES];  // gx1
__device__ float g_h0 [(size_t)BATCH * T_STEPS * HID];
__device__ float g_h1 [(size_t)BATCH * T_STEPS * HID];
__device__ float g_h2 [(size_t)BATCH * T_STEPS * HID];
__device__ int   g_syn[64 + 2 + BATCH * NCHUNK * 2];      // prog0, ctrA/B, chunk1, chunk2

// ---------------------------------------------------------------------------
// GEMM tile machinery (bf16 3-product split, fp32 acc, ldmatrix)
// ---------------------------------------------------------------------------
#define SR 136   // padded bf16 row stride

__device__ __forceinline__ void mma_bf16(float* d, const unsigned* a, const unsigned* b) {
    asm volatile(
        "mma.sync.aligned.m16n8k16.row.col.f32.bf16.bf16.f32 "
        "{%0,%1,%2,%3}, {%4,%5,%6,%7}, {%8,%9}, {%0,%1,%2,%3};"
        : "+f"(d[0]), "+f"(d[1]), "+f"(d[2]), "+f"(d[3])
        : "r"(a[0]), "r"(a[1]), "r"(a[2]), "r"(a[3]), "r"(b[0]), "r"(b[1]));
}
__device__ __forceinline__ void ldsm_x4(unsigned* r, unsigned addr) {
    asm volatile("ldmatrix.sync.aligned.m8n8.x4.shared.b16 {%0,%1,%2,%3}, [%4];"
                 : "=r"(r[0]), "=r"(r[1]), "=r"(r[2]), "=r"(r[3]) : "r"(addr));
}

__device__ void gemm_tile(const float* __restrict__ A, const float* __restrict__ W,
                          const float* __restrict__ bih, const float* __restrict__ bhh,
                          float* __restrict__ out, int brow, int bcol, char* gsm)
{
    __nv_bfloat16* a_hi = (__nv_bfloat16*)gsm;                  // [128][SR]
    __nv_bfloat16* a_lo = a_hi + 128 * SR;
    __nv_bfloat16* w_hi = a_lo + 128 * SR;
    __nv_bfloat16* w_lo = w_hi + 128 * SR;
    float*         bias_s = (float*)(w_lo + 128 * SR);          // [128]

    const int tid = threadIdx.x;
    if (tid < 128) bias_s[tid] = bih[bcol + tid] + bhh[bcol + tid];

    {
        const int row = tid >> 1;
        const int cb  = (tid & 1) * 64;
        const float* Ar = A + (size_t)(brow + row) * HID + cb;
        const float* Wr = W + (size_t)(bcol + row) * HID + cb;
        __nv_bfloat16* ah = a_hi + row * SR + cb;
        __nv_bfloat16* al = a_lo + row * SR + cb;
        __nv_bfloat16* wh = w_hi + row * SR + cb;
        __nv_bfloat16* wl = w_lo + row * SR + cb;
#pragma unroll 4
        for (int c = 0; c < 64; c += 4) {
            float4 v = *(const float4*)(Ar + c);
            __nv_bfloat16 hx = __float2bfloat16_rn(v.x);
            __nv_bfloat16 hy = __float2bfloat16_rn(v.y);
            __nv_bfloat16 hz = __float2bfloat16_rn(v.z);
            __nv_bfloat16 hw = __float2bfloat16_rn(v.w);
            __nv_bfloat162 H0; H0.x = hx; H0.y = hy;
            __nv_bfloat162 H1; H1.x = hz; H1.y = hw;
            __nv_bfloat162 L0 = __floats2bfloat162_rn(v.x - __bfloat162float(hx),
                                                      v.y - __bfloat162float(hy));
            __nv_bfloat162 L1 = __floats2bfloat162_rn(v.z - __bfloat162float(hz),
                                                      v.w - __bfloat162float(hw));
            *(__nv_bfloat162*)(ah + c)     = H0;
            *(__nv_bfloat162*)(ah + c + 2) = H1;
            *(__nv_bfloat162*)(al + c)     = L0;
            *(__nv_bfloat162*)(al + c + 2) = L1;

            float4 u = *(const float4*)(Wr + c);
            __nv_bfloat16 gx = __float2bfloat16_rn(u.x);
            __nv_bfloat16 gy = __float2bfloat16_rn(u.y);
            __nv_bfloat16 gz = __float2bfloat16_rn(u.z);
            __nv_bfloat16 gw = __float2bfloat16_rn(u.w);
            __nv_bfloat162 G0; G0.x = gx; G0.y = gy;
            __nv_bfloat162 G1; G1.x = gz; G1.y = gw;
            __nv_bfloat162 M0 = __floats2bfloat162_rn(u.x - __bfloat162float(gx),
                                                      u.y - __bfloat162float(gy));
            __nv_bfloat162 M1 = __floats2bfloat162_rn(u.z - __bfloat162float(gz),
                                                      u.w - __bfloat162float(gw));
            *(__nv_bfloat162*)(wh + c)     = G0;
            *(__nv_bfloat162*)(wh + c + 2) = G1;
            *(__nv_bfloat162*)(wl + c)     = M0;
            *(__nv_bfloat162*)(wl + c + 2) = M1;
        }
    }
    __syncthreads();

    const int wid    = tid >> 5;
    const int lane   = tid & 31;
    const int warp_m = wid >> 1;
    const int warp_n = wid & 1;
    const int m_base = warp_m * 32;
    const int n_base = warp_n * 64;

    const unsigned a_hi_s = (unsigned)__cvta_generic_to_shared(a_hi);
    const unsigned a_lo_s = (unsigned)__cvta_generic_to_shared(a_lo);
    const unsigned w_hi_s = (unsigned)__cvta_generic_to_shared(w_hi);
    const unsigned w_lo_s = (unsigned)__cvta_generic_to_shared(w_lo);

    const int arow  = m_base + (lane & 15);
    const int akoff = (lane >> 4) * 8;
    const int gsel  = lane >> 3;
    const int brow_ = n_base + ((gsel >> 1) & 1) * 8 + (lane & 7);
    const int bkoff = (gsel & 1) * 8;

    float d[2][8][4];
#pragma unroll
    for (int mi = 0; mi < 2; mi++)
#pragma unroll
        for (int ni = 0; ni < 8; ni++)
#pragma unroll
            for (int e = 0; e < 4; e++) d[mi][ni][e] = 0.f;

#pragma unroll
    for (int k0 = 0; k0 < HID; k0 += 16) {
        unsigned ah[2][4], al[2][4];
#pragma unroll
        for (int mi = 0; mi < 2; mi++) {
            unsigned off = (unsigned)(((arow + mi * 16) * SR + akoff + k0) * 2);
            ldsm_x4(ah[mi], a_hi_s + off);
            ldsm_x4(al[mi], a_lo_s + off);
        }
        unsigned bh[4][4], bl[4][4];
#pragma unroll
        for (int nb = 0; nb < 4; nb++) {
            unsigned off = (unsigned)(((brow_ + nb * 16) * SR + bkoff + k0) * 2);
            ldsm_x4(bh[nb], w_hi_s + off);
            ldsm_x4(bl[nb], w_lo_s + off);
        }
#pragma unroll
        for (int mi = 0; mi < 2; mi++)
#pragma unroll
            for (int nb = 0; nb < 4; nb++) {
                mma_bf16(d[mi][2 * nb],     ah[mi], &bh[nb][0]);
                mma_bf16(d[mi][2 * nb],     ah[mi], &bl[nb][0]);
                mma_bf16(d[mi][2 * nb],     al[mi], &bh[nb][0]);
                mma_bf16(d[mi][2 * nb + 1], ah[mi], &bh[nb][2]);
                mma_bf16(d[mi][2 * nb + 1], ah[mi], &bl[nb][2]);
                mma_bf16(d[mi][2 * nb + 1], al[mi], &bh[nb][2]);
            }
    }

    const int tr = lane >> 2;
    const int tc = (lane & 3) * 2;
#pragma unroll
    for (int mi = 0; mi < 2; mi++) {
        int gr0 = brow + m_base + mi * 16 + tr;
#pragma unroll
        for (int ni = 0; ni < 8; ni++) {
            int lc = n_base + ni * 8 + tc;
            float2 bv = *(const float2*)&bias_s[lc];
            float2 o0 = {d[mi][ni][0] + bv.x, d[mi][ni][1] + bv.y};
            float2 o1 = {d[mi][ni][2] + bv.x, d[mi][ni][3] + bv.y};
            *(float2*)(out + (size_t)gr0 * GATES + bcol + lc)       = o0;
            *(float2*)(out + (size_t)(gr0 + 8) * GATES + bcol + lc) = o1;
        }
    }
}

// Standalone layer-0 GEMM over the whole input
__global__ __launch_bounds__(256) void gemm0_kernel(
    const float* __restrict__ A, const float* __restrict__ W,
    const float* __restrict__ bih, const float* __restrict__ bhh)
{
    extern __shared__ char gsm[];
    gemm_tile(A, W, bih, bhh, g_gxA, blockIdx.x * 128, blockIdx.y * 128, gsm);
}

// ---------------------------------------------------------------------------
// Recurrence body (R3 structure, measured best). Optional:
//  - prog:       publish progress every 64 steps (h producer role)
//  - chunkready: gate gx consumption per 128-step chunk (4 tiles per chunk)
// ---------------------------------------------------------------------------
__device__ __forceinline__ float sigm(float x) {
    return __fdividef(1.f, 1.f + __expf(-x));
}
__device__ __forceinline__ float tanh_fast(float x) {
    float e = __expf(2.f * x);
    return 1.f - __fdividef(2.f, e + 1.f);
}

__device__ void rec_body(const float* __restrict__ whh, const float* __restrict__ gx,
                         float* __restrict__ hout, int* __restrict__ prog,
                         const int* __restrict__ chunkready, int b, char* smraw)
{
    ull*   ws2 = (ull*)smraw;                    // [SKP][512] pair-major weight pairs
    float* g_s = (float*)(ws2 + SKP * 512);      // 512 gate pre-activations
    float* h_s = g_s + GATES;                    // 128 hidden state

    const int tid = threadIdx.x;
    const int r0  = tid;
    const int r1  = tid + 256;

    ull wa2[RKP], wb2[RKP];
    {
        const ull* wp0 = (const ull*)(whh + (size_t)r0 * HID);
        const ull* wp1 = (const ull*)(whh + (size_t)r1 * HID);
#pragma unroll
        for (int q = 0; q < RKP; q++) { wa2[q] = wp0[q]; wb2[q] = wp1[q]; }
    }
    for (int idx = tid; idx < SKP * 512; idx += 256) {
        int r = idx & 511, p = idx >> 9;
        ws2[idx] = ((const ull*)(whh + (size_t)r * HID))[RKP + p];
    }
    if (tid < HID) h_s[tid] = 0.f;
    float c = 0.f;
    __syncthreads();

    const float* gxb = gx   + (size_t)b * T_STEPS * GATES;
    float*       hb  = hout + (size_t)b * T_STEPS * HID;

    float nga = 0.f, ngb = 0.f;
    if (!chunkready) { nga = gxb[r0]; ngb = gxb[r1]; }

    for (int t = 0; t < T_STEPS; t++) {
        if (chunkready && (t & (CHSTEP - 1)) == 0) {
            if (tid == 0) {
                const int* cw = chunkready + b * NCHUNK + (t >> 7);
                while (ld_acquire_gpu(cw) < 4) __nanosleep(128);
            }
            __syncthreads();
            nga = __ldg(gxb + (size_t)t * GATES + r0);
            ngb = __ldg(gxb + (size_t)t * GATES + r1);
        }
        ull acc0 = pack2(nga, 0.f);
        ull acc1 = pack2(ngb, 0.f);
        if (t + 1 < T_STEPS && (!chunkready || ((t + 1) & (CHSTEP - 1)) != 0)) {
            nga = __ldg(gxb + (size_t)(t + 1) * GATES + r0);
            ngb = __ldg(gxb + (size_t)(t + 1) * GATES + r1);
        }
        const ull* h2 = (const ull*)h_s;   // 64 packed h pairs (broadcast LDS.64)
#pragma unroll
        for (int q = 0; q < RKP; q++) {
            ull hp = h2[q];
            acc0 = ffma2(hp, wa2[q], acc0);
            acc1 = ffma2(hp, wb2[q], acc1);
        }
#pragma unroll
        for (int p = 0; p < SKP; p++) {
            ull hp = h2[RKP + p];
            acc0 = ffma2(hp, ws2[p * 512 + r0], acc0);
            acc1 = ffma2(hp, ws2[p * 512 + r1], acc1);
        }
        float2 v0 = unpack2(acc0);
        float2 v1 = unpack2(acc1);
        g_s[r0] = v0.x + v0.y;
        g_s[r1] = v1.x + v1.y;
        __syncthreads();
        if (tid < 128) {
            float i_ = sigm(g_s[tid]);
            float f_ = sigm(g_s[tid + 128]);
            float g_ = tanh_fast(g_s[tid + 256]);
            float o_ = sigm(g_s[tid + 384]);
            c = fmaf(f_, c, i_ * g_);
            float hv = o_ * tanh_fast(c);
            h_s[tid] = hv;
            hb[(size_t)t * HID + tid] = hv;
        }
        bool pub = prog && ((t & 63) == 63);
        if (pub) __threadfence();          // all threads: release h writes
        __syncthreads();
        if (pub && tid == 0) atomicExch(prog + b, t + 1);
    }
}

// ---------------------------------------------------------------------------
// GEMM worker: pulls 128x128 tiles from an atomic pool (chunk-major order).
// Optionally paced by producer progress (prog0). Publishes per-(b,chunk)
// completion counters for downstream rec gating.
// ---------------------------------------------------------------------------
__device__ void gemm_worker(const float* __restrict__ W,
                            const float* __restrict__ bih, const float* __restrict__ bhh,
                            float* __restrict__ out, const float* __restrict__ hsrc,
                            int* __restrict__ prog0, int* __restrict__ ctr,
                            int* __restrict__ chunkdone, char* gsm)
{
    const int tid = threadIdx.x;
    __shared__ int s_idx;
    const int NT = NCHUNK * BATCH * 4;   // 4096 tiles
    while (true) {
        if (tid == 0) s_idx = atomicAdd(ctr, 1);
        __syncthreads();
        int idx = s_idx;
        __syncthreads();
        if (idx >= NT) break;
        int chunk = idx >> 8;            // 0..15
        int b     = (idx >> 2) & 63;
        int cy    = idx & 3;
        if (prog0) {
            if (tid == 0) {
                int need = (chunk + 1) * CHSTEP;
                int v;
                while (true) {
                    asm volatile("ld.global.cg.u32 %0, [%1];" : "=r"(v) : "l"(prog0 + b));
                    if (v >= need) break;
                    __nanosleep(256);
                }
                __threadfence();
            }
            __syncthreads();
        }
        gemm_tile(hsrc, W, bih, bhh, out, b * T_STEPS + chunk * CHSTEP, cy * 128, gsm);
        __threadfence();                 // all threads: release tile stores
        __syncthreads();
        if (tid == 0) atomicAdd(chunkdone + b * NCHUNK + chunk, 1);
    }
}

// ---------------------------------------------------------------------------
// K_A: blocks [0,64)  = rec layer 0 (producer; joins gemm pool when done)
//      blocks [64,128)= rec layer 1 (chunk-gated on gx1)
//      blocks [128,148)= gemm1 workers (h0 -> gx1), paced by prog0
// ---------------------------------------------------------------------------
__global__ __launch_bounds__(256, 1) void kernelA(
    const float* __restrict__ whh0, const float* __restrict__ whh1,
    const float* __restrict__ gx0, float* __restrict__ gx1,
    const float* __restrict__ wih1, const float* __restrict__ bih1,
    const float* __restrict__ bhh1,
    int* __restrict__ prog0, int* __restrict__ ctrA, int* __restrict__ chunk1)
{
    extern __shared__ char smraw[];
    if (blockIdx.x < BATCH) {
        rec_body(whh0, gx0, g_h0, prog0, nullptr, blockIdx.x, smraw);
        __syncthreads();
        gemm_worker(wih1, bih1, bhh1, gx1, g_h0, prog0, ctrA, chunk1, smraw);
    } else if (blockIdx.x < 2 * BATCH) {
        rec_body(whh1, gx1, g_h1, nullptr, chunk1, blockIdx.x - BATCH, smraw);
    } else {
        gemm_worker(wih1, bih1, bhh1, gx1, g_h0, prog0, ctrA, chunk1, smraw);
    }
}

// ---------------------------------------------------------------------------
// K_B: blocks [0,64)  = rec layer 2 (chunk-gated on gx2)
//      blocks [64,148)= gemm2 workers (h1 -> gx2), unpaced (h1 complete)
// ---------------------------------------------------------------------------
__global__ __launch_bounds__(256, 1) void kernelB(
    const float* __restrict__ whh2, float* __restrict__ gx2,
    const float* __restrict__ wih2, const float* __restrict__ bih2,
    const float* __restrict__ bhh2,
    int* __restrict__ ctrB, int* __restrict__ chunk2)
{
    extern __shared__ char smraw[];
    if (blockIdx.x < BATCH) {
        rec_body(whh2, gx2, g_h2, nullptr, chunk2, blockIdx.x, smraw);
    } else {
        gemm_worker(wih2, bih2, bhh2, gx2, g_h1, nullptr, ctrB, chunk2, smraw);
    }
}

// ---------------------------------------------------------------------------
// MLP head: h_last[64,128] -> 64 -> 32 -> 10 (all linear)
// ---------------------------------------------------------------------------
__global__ __launch_bounds__(256) void mlp_kernel(
    const float* __restrict__ w1, const float* __restrict__ b1,
    const float* __restrict__ w2, const float* __restrict__ b2,
    const float* __restrict__ w3, const float* __restrict__ b3,
    float* __restrict__ out)
{
    extern __shared__ float sm[];
    float* hs = sm;          // 64*128, later reused for y2 (64*32)
    float* y1 = sm + 8192;   // 64*64

    const int tid = threadIdx.x;
    for (int idx = tid; idx < 8192; idx += 256) {
        int b = idx >> 7, j = idx & 127;
        hs[idx] = g_h2[(size_t)b * T_STEPS * HID + (size_t)(T_STEPS - 1) * HID + j];
    }
    __syncthreads();
    for (int idx = tid; idx < 4096; idx += 256) {
        int b = idx >> 6, o = idx & 63;
        float s = b1[o];
#pragma unroll 8
        for (int k = 0; k < 128; k++) s = fmaf(hs[b * 128 + k], w1[o * 128 + k], s);
        y1[idx] = s;
    }
    __syncthreads();
    for (int idx = tid; idx < 2048; idx += 256) {
        int b = idx >> 5, o = idx & 31;
        float s = b2[o];
#pragma unroll 8
        for (int k = 0; k < 64; k++) s = fmaf(y1[b * 64 + k], w2[o * 64 + k], s);
        hs[idx] = s;  // reuse hs as y2 [64,32]
    }
    __syncthreads();
    for (int idx = tid; idx < 640; idx += 256) {
        int b = idx / 10, o = idx % 10;
        float s = b3[o];
#pragma unroll
        for (int k = 0; k < 32; k++) s = fmaf(hs[b * 32 + k], w3[o * 32 + k], s);
        out[idx] = s;
    }
}

// ---------------------------------------------------------------------------
extern "C" void kernel_launch(void* const* d_in, const int* in_sizes, int n_in,
                              void* d_out, int out_size)
{
    (void)in_sizes; (void)n_in; (void)out_size;
    const float* x   = (const float*)d_in[0];
    const float* wih = (const float*)d_in[1];
    const float* whh = (const float*)d_in[2];
    const float* bih = (const float*)d_in[3];
    const float* bhh = (const float*)d_in[4];
    const float* w1  = (const float*)d_in[5];
    const float* b1  = (const float*)d_in[6];
    const float* w2  = (const float*)d_in[7];
    const float* b2  = (const float*)d_in[8];
    const float* w3  = (const float*)d_in[9];
    const float* b3  = (const float*)d_in[10];

    void *pA = nullptr, *pB = nullptr, *pS = nullptr;
    cudaGetSymbolAddress(&pA, g_gxA);
    cudaGetSymbolAddress(&pB, g_gxB);
    cudaGetSymbolAddress(&pS, g_syn);
    float* bufA = (float*)pA;   // gx0, then gx2
    float* bufB = (float*)pB;   // gx1
    int*   syn  = (int*)pS;

    int* prog0  = syn;                    // [64]
    int* ctrA   = syn + 64;               // gemm1 tile pool
    int* ctrB   = syn + 65;               // gemm2 tile pool
    int* chunk1 = syn + 66;               // [64*16]
    int* chunk2 = chunk1 + BATCH * NCHUNK;

    const int GEMM_SMEM = 4 * 128 * SR * 2 + 128 * 4;   // 139,776 B
    const int MLP_SMEM  = (8192 + 4096) * 4;            // 48 KB
    cudaFuncSetAttribute(gemm0_kernel, cudaFuncAttributeMaxDynamicSharedMemorySize, GEMM_SMEM);
    cudaFuncSetAttribute(kernelA,      cudaFuncAttributeMaxDynamicSharedMemorySize, GEMM_SMEM);
    cudaFuncSetAttribute(kernelB,      cudaFuncAttributeMaxDynamicSharedMemorySize, GEMM_SMEM);
    cudaFuncSetAttribute(mlp_kernel,   cudaFuncAttributeMaxDynamicSharedMemorySize, MLP_SMEM);

    cudaMemsetAsync(syn, 0, (66 + 2 * BATCH * NCHUNK) * sizeof(int));

    const size_t WSZ = (size_t)GATES * HID;

    // gx0 = x @ wih0^T + biases  -> bufA
    gemm0_kernel<<<dim3(BATCH * T_STEPS / 128, 4), 256, GEMM_SMEM>>>(
        x, wih, bih, bhh);

    // K_A: rec0 (writes h0, publishes prog0)  ||  gemm1 (h0->gx1=bufB, paced)
    //      ||  rec1 (consumes gx1 chunk-gated, writes h1)
    kernelA<<<NSM, 256, GEMM_SMEM>>>(
        whh, whh + WSZ, bufA, bufB,
        wih + WSZ, bih + GATES, bhh + GATES,
        prog0, ctrA, chunk1);

    // K_B: gemm2 (h1->gx2=bufA, unpaced)  ||  rec2 (chunk-gated, writes h2)
    kernelB<<<NSM, 256, GEMM_SMEM>>>(
        whh + 2 * WSZ, bufA,
        wih + 2 * WSZ, bih + 2 * GATES, bhh + 2 * GATES,
        ctrB, chunk2);

    mlp_kernel<<<1, 256, MLP_SMEM>>>(w1, b1, w2, b2, w3, b3, (float*)d_out);
}

// round 13
// speedup vs baseline: 1.3373x; 1.0052x over previous
#include <cuda_runtime.h>
#include <cuda_bf16.h>
#include <cstddef>

#define T_STEPS 2048
#define BATCH   64
#define HID     128
#define GATES   512          // 4*HID
#define RK      96           // k-values in registers (as pairs)
#define RKP     (RK/2)       // 48 register pairs
#define SK      (HID - RK)   // 32 k-values in smem
#define SKP     (SK/2)       // 16 smem pairs
#define NSM     148
#define NCHUNK  16           // 2048 / 128
#define CHSTEP  128

typedef unsigned long long ull;

// ---- packed fp32x2 helpers (sm_100+) --------------------------------------
__device__ __forceinline__ ull ffma2(ull a, ull b, ull c) {
    ull d;
    asm("fma.rn.f32x2 %0, %1, %2, %3;" : "=l"(d) : "l"(a), "l"(b), "l"(c));
    return d;
}
__device__ __forceinline__ ull pack2(float lo, float hi) {
    ull r; asm("mov.b64 %0, {%1, %2};" : "=l"(r) : "f"(lo), "f"(hi)); return r;
}
__device__ __forceinline__ float2 unpack2(ull v) {
    float2 f; asm("mov.b64 {%0, %1}, %2;" : "=f"(f.x), "=f"(f.y) : "l"(v)); return f;
}
__device__ __forceinline__ int ld_acquire_gpu(const int* p) {
    int v;
    asm volatile("ld.acquire.gpu.global.s32 %0, [%1];" : "=r"(v) : "l"(p) : "memory");
    return v;
}

// Scratch (device globals; no allocations allowed)
__device__ float g_gxA[(size_t)BATCH * T_STEPS * GATES];  // gx0, then reused for gx2
__device__ float g_gxB[(size_t)BATCH * T_STEPS * GATES];  // gx1
__device__ float g_h0 [(size_t)BATCH * T_STEPS * HID];
__device__ float g_h1 [(size_t)BATCH * T_STEPS * HID];
__device__ float g_h2 [(size_t)BATCH * T_STEPS * HID];
__device__ int   g_syn[130 + BATCH * NCHUNK * 2];  // prog0[64] prog1[64] ctrA ctrB chunk1 chunk2

// ---------------------------------------------------------------------------
// GEMM tile machinery (bf16 3-product split, fp32 acc, ldmatrix)
// ---------------------------------------------------------------------------
#define SR 136   // padded bf16 row stride

__device__ __forceinline__ void mma_bf16(float* d, const unsigned* a, const unsigned* b) {
    asm volatile(
        "mma.sync.aligned.m16n8k16.row.col.f32.bf16.bf16.f32 "
        "{%0,%1,%2,%3}, {%4,%5,%6,%7}, {%8,%9}, {%0,%1,%2,%3};"
        : "+f"(d[0]), "+f"(d[1]), "+f"(d[2]), "+f"(d[3])
        : "r"(a[0]), "r"(a[1]), "r"(a[2]), "r"(a[3]), "r"(b[0]), "r"(b[1]));
}
__device__ __forceinline__ void ldsm_x4(unsigned* r, unsigned addr) {
    asm volatile("ldmatrix.sync.aligned.m8n8.x4.shared.b16 {%0,%1,%2,%3}, [%4];"
                 : "=r"(r[0]), "=r"(r[1]), "=r"(r[2]), "=r"(r[3]) : "r"(addr));
}

__device__ void gemm_tile(const float* __restrict__ A, const float* __restrict__ W,
                          const float* __restrict__ bih, const float* __restrict__ bhh,
                          float* __restrict__ out, int brow, int bcol, char* gsm)
{
    __nv_bfloat16* a_hi = (__nv_bfloat16*)gsm;                  // [128][SR]
    __nv_bfloat16* a_lo = a_hi + 128 * SR;
    __nv_bfloat16* w_hi = a_lo + 128 * SR;
    __nv_bfloat16* w_lo = w_hi + 128 * SR;
    float*         bias_s = (float*)(w_lo + 128 * SR);          // [128]

    const int tid = threadIdx.x;
    if (tid < 128) bias_s[tid] = bih[bcol + tid] + bhh[bcol + tid];

    {
        const int row = tid >> 1;
        const int cb  = (tid & 1) * 64;
        const float* Ar = A + (size_t)(brow + row) * HID + cb;
        const float* Wr = W + (size_t)(bcol + row) * HID + cb;
        __nv_bfloat16* ah = a_hi + row * SR + cb;
        __nv_bfloat16* al = a_lo + row * SR + cb;
        __nv_bfloat16* wh = w_hi + row * SR + cb;
        __nv_bfloat16* wl = w_lo + row * SR + cb;
#pragma unroll 4
        for (int c = 0; c < 64; c += 4) {
            float4 v = *(const float4*)(Ar + c);
            __nv_bfloat16 hx = __float2bfloat16_rn(v.x);
            __nv_bfloat16 hy = __float2bfloat16_rn(v.y);
            __nv_bfloat16 hz = __float2bfloat16_rn(v.z);
            __nv_bfloat16 hw = __float2bfloat16_rn(v.w);
            __nv_bfloat162 H0; H0.x = hx; H0.y = hy;
            __nv_bfloat162 H1; H1.x = hz; H1.y = hw;
            __nv_bfloat162 L0 = __floats2bfloat162_rn(v.x - __bfloat162float(hx),
                                                      v.y - __bfloat162float(hy));
            __nv_bfloat162 L1 = __floats2bfloat162_rn(v.z - __bfloat162float(hz),
                                                      v.w - __bfloat162float(hw));
            *(__nv_bfloat162*)(ah + c)     = H0;
            *(__nv_bfloat162*)(ah + c + 2) = H1;
            *(__nv_bfloat162*)(al + c)     = L0;
            *(__nv_bfloat162*)(al + c + 2) = L1;

            float4 u = *(const float4*)(Wr + c);
            __nv_bfloat16 gx = __float2bfloat16_rn(u.x);
            __nv_bfloat16 gy = __float2bfloat16_rn(u.y);
            __nv_bfloat16 gz = __float2bfloat16_rn(u.z);
            __nv_bfloat16 gw = __float2bfloat16_rn(u.w);
            __nv_bfloat162 G0; G0.x = gx; G0.y = gy;
            __nv_bfloat162 G1; G1.x = gz; G1.y = gw;
            __nv_bfloat162 M0 = __floats2bfloat162_rn(u.x - __bfloat162float(gx),
                                                      u.y - __bfloat162float(gy));
            __nv_bfloat162 M1 = __floats2bfloat162_rn(u.z - __bfloat162float(gz),
                                                      u.w - __bfloat162float(gw));
            *(__nv_bfloat162*)(wh + c)     = G0;
            *(__nv_bfloat162*)(wh + c + 2) = G1;
            *(__nv_bfloat162*)(wl + c)     = M0;
            *(__nv_bfloat162*)(wl + c + 2) = M1;
        }
    }
    __syncthreads();

    const int wid    = tid >> 5;
    const int lane   = tid & 31;
    const int warp_m = wid >> 1;
    const int warp_n = wid & 1;
    const int m_base = warp_m * 32;
    const int n_base = warp_n * 64;

    const unsigned a_hi_s = (unsigned)__cvta_generic_to_shared(a_hi);
    const unsigned a_lo_s = (unsigned)__cvta_generic_to_shared(a_lo);
    const unsigned w_hi_s = (unsigned)__cvta_generic_to_shared(w_hi);
    const unsigned w_lo_s = (unsigned)__cvta_generic_to_shared(w_lo);

    const int arow  = m_base + (lane & 15);
    const int akoff = (lane >> 4) * 8;
    const int gsel  = lane >> 3;
    const int brow_ = n_base + ((gsel >> 1) & 1) * 8 + (lane & 7);
    const int bkoff = (gsel & 1) * 8;

    float d[2][8][4];
#pragma unroll
    for (int mi = 0; mi < 2; mi++)
#pragma unroll
        for (int ni = 0; ni < 8; ni++)
#pragma unroll
            for (int e = 0; e < 4; e++) d[mi][ni][e] = 0.f;

#pragma unroll
    for (int k0 = 0; k0 < HID; k0 += 16) {
        unsigned ah[2][4], al[2][4];
#pragma unroll
        for (int mi = 0; mi < 2; mi++) {
            unsigned off = (unsigned)(((arow + mi * 16) * SR + akoff + k0) * 2);
            ldsm_x4(ah[mi], a_hi_s + off);
            ldsm_x4(al[mi], a_lo_s + off);
        }
        unsigned bh[4][4], bl[4][4];
#pragma unroll
        for (int nb = 0; nb < 4; nb++) {
            unsigned off = (unsigned)(((brow_ + nb * 16) * SR + bkoff + k0) * 2);
            ldsm_x4(bh[nb], w_hi_s + off);
            ldsm_x4(bl[nb], w_lo_s + off);
        }
#pragma unroll
        for (int mi = 0; mi < 2; mi++)
#pragma unroll
            for (int nb = 0; nb < 4; nb++) {
                mma_bf16(d[mi][2 * nb],     ah[mi], &bh[nb][0]);
                mma_bf16(d[mi][2 * nb],     ah[mi], &bl[nb][0]);
                mma_bf16(d[mi][2 * nb],     al[mi], &bh[nb][0]);
                mma_bf16(d[mi][2 * nb + 1], ah[mi], &bh[nb][2]);
                mma_bf16(d[mi][2 * nb + 1], ah[mi], &bl[nb][2]);
                mma_bf16(d[mi][2 * nb + 1], al[mi], &bh[nb][2]);
            }
    }

    const int tr = lane >> 2;
    const int tc = (lane & 3) * 2;
#pragma unroll
    for (int mi = 0; mi < 2; mi++) {
        int gr0 = brow + m_base + mi * 16 + tr;
#pragma unroll
        for (int ni = 0; ni < 8; ni++) {
            int lc = n_base + ni * 8 + tc;
            float2 bv = *(const float2*)&bias_s[lc];
            float2 o0 = {d[mi][ni][0] + bv.x, d[mi][ni][1] + bv.y};
            float2 o1 = {d[mi][ni][2] + bv.x, d[mi][ni][3] + bv.y};
            *(float2*)(out + (size_t)gr0 * GATES + bcol + lc)       = o0;
            *(float2*)(out + (size_t)(gr0 + 8) * GATES + bcol + lc) = o1;
        }
    }
}

// Standalone layer-0 GEMM over the whole input
__global__ __launch_bounds__(256) void gemm0_kernel(
    const float* __restrict__ A, const float* __restrict__ W,
    const float* __restrict__ bih, const float* __restrict__ bhh)
{
    extern __shared__ char gsm[];
    gemm_tile(A, W, bih, bhh, g_gxA, blockIdx.x * 128, blockIdx.y * 128, gsm);
}

// ---------------------------------------------------------------------------
// Recurrence body (R3 structure, measured best). Optional:
//  - prog:       publish progress every 64 steps (h producer role)
//  - chunkready: gate gx consumption per 128-step chunk (4 tiles per chunk)
// ---------------------------------------------------------------------------
__device__ __forceinline__ float sigm(float x) {
    return __fdividef(1.f, 1.f + __expf(-x));
}
__device__ __forceinline__ float tanh_fast(float x) {
    float e = __expf(2.f * x);
    return 1.f - __fdividef(2.f, e + 1.f);
}

__device__ void rec_body(const float* __restrict__ whh, const float* __restrict__ gx,
                         float* __restrict__ hout, int* __restrict__ prog,
                         const int* __restrict__ chunkready, int b, char* smraw)
{
    ull*   ws2 = (ull*)smraw;                    // [SKP][512] pair-major weight pairs
    float* g_s = (float*)(ws2 + SKP * 512);      // 512 gate pre-activations
    float* h_s = g_s + GATES;                    // 128 hidden state

    const int tid = threadIdx.x;
    const int r0  = tid;
    const int r1  = tid + 256;

    ull wa2[RKP], wb2[RKP];
    {
        const ull* wp0 = (const ull*)(whh + (size_t)r0 * HID);
        const ull* wp1 = (const ull*)(whh + (size_t)r1 * HID);
#pragma unroll
        for (int q = 0; q < RKP; q++) { wa2[q] = wp0[q]; wb2[q] = wp1[q]; }
    }
    for (int idx = tid; idx < SKP * 512; idx += 256) {
        int r = idx & 511, p = idx >> 9;
        ws2[idx] = ((const ull*)(whh + (size_t)r * HID))[RKP + p];
    }
    if (tid < HID) h_s[tid] = 0.f;
    float c = 0.f;
    __syncthreads();

    const float* gxb = gx   + (size_t)b * T_STEPS * GATES;
    float*       hb  = hout + (size_t)b * T_STEPS * HID;

    float nga = 0.f, ngb = 0.f;
    if (!chunkready) { nga = gxb[r0]; ngb = gxb[r1]; }

    for (int t = 0; t < T_STEPS; t++) {
        if (chunkready && (t & (CHSTEP - 1)) == 0) {
            if (tid == 0) {
                const int* cw = chunkready + b * NCHUNK + (t >> 7);
                while (ld_acquire_gpu(cw) < 4) __nanosleep(128);
            }
            __syncthreads();
            nga = __ldg(gxb + (size_t)t * GATES + r0);
            ngb = __ldg(gxb + (size_t)t * GATES + r1);
        }
        ull acc0 = pack2(nga, 0.f);
        ull acc1 = pack2(ngb, 0.f);
        if (t + 1 < T_STEPS && (!chunkready || ((t + 1) & (CHSTEP - 1)) != 0)) {
            nga = __ldg(gxb + (size_t)(t + 1) * GATES + r0);
            ngb = __ldg(gxb + (size_t)(t + 1) * GATES + r1);
        }
        const ull* h2 = (const ull*)h_s;   // 64 packed h pairs (broadcast LDS.64)
#pragma unroll
        for (int q = 0; q < RKP; q++) {
            ull hp = h2[q];
            acc0 = ffma2(hp, wa2[q], acc0);
            acc1 = ffma2(hp, wb2[q], acc1);
        }
#pragma unroll
        for (int p = 0; p < SKP; p++) {
            ull hp = h2[RKP + p];
            acc0 = ffma2(hp, ws2[p * 512 + r0], acc0);
            acc1 = ffma2(hp, ws2[p * 512 + r1], acc1);
        }
        float2 v0 = unpack2(acc0);
        float2 v1 = unpack2(acc1);
        g_s[r0] = v0.x + v0.y;
        g_s[r1] = v1.x + v1.y;
        __syncthreads();
        if (tid < 128) {
            float i_ = sigm(g_s[tid]);
            float f_ = sigm(g_s[tid + 128]);
            float g_ = tanh_fast(g_s[tid + 256]);
            float o_ = sigm(g_s[tid + 384]);
            c = fmaf(f_, c, i_ * g_);
            float hv = o_ * tanh_fast(c);
            h_s[tid] = hv;
            hb[(size_t)t * HID + tid] = hv;
        }
        bool pub = prog && ((t & 63) == 63);
        if (pub) __threadfence();          // all threads: release h writes
        __syncthreads();
        if (pub && tid == 0) atomicExch(prog + b, t + 1);
    }
}

// ---------------------------------------------------------------------------
// GEMM worker: pulls 128x128 tiles from an atomic pool (chunk-major order),
// paced by producer progress (prog). Publishes per-(b,chunk) counters.
// ---------------------------------------------------------------------------
__device__ void gemm_worker(const float* __restrict__ W,
                            const float* __restrict__ bih, const float* __restrict__ bhh,
                            float* __restrict__ out, const float* __restrict__ hsrc,
                            int* __restrict__ prog, int* __restrict__ ctr,
                            int* __restrict__ chunkdone, char* gsm)
{
    const int tid = threadIdx.x;
    __shared__ int s_idx;
    const int NT = NCHUNK * BATCH * 4;   // 4096 tiles
    while (true) {
        if (tid == 0) s_idx = atomicAdd(ctr, 1);
        __syncthreads();
        int idx = s_idx;
        __syncthreads();
        if (idx >= NT) break;
        int chunk = idx >> 8;            // 0..15
        int b     = (idx >> 2) & 63;
        int cy    = idx & 3;
        if (tid == 0) {
            int need = (chunk + 1) * CHSTEP;
            int v;
            while (true) {
                asm volatile("ld.global.cg.u32 %0, [%1];" : "=r"(v) : "l"(prog + b));
                if (v >= need) break;
                __nanosleep(256);
            }
            __threadfence();
        }
        __syncthreads();
        gemm_tile(hsrc, W, bih, bhh, out, b * T_STEPS + chunk * CHSTEP, cy * 128, gsm);
        __threadfence();                 // all threads: release tile stores
        __syncthreads();
        if (tid == 0) atomicAdd(chunkdone + b * NCHUNK + chunk, 1);
    }
}

// ---------------------------------------------------------------------------
// Mega kernel: all three rec layers pipelined in one launch.
//  blocks [0,64):    rec0 (publishes prog0) then rec2 (gated on chunk2)
//  blocks [64,128):  rec1 (gated on chunk1, publishes prog1), then gemm pools
//  blocks [128,148): gemm1 pool (h0->gx1), then gemm2 pool (h1->gx2)
// gx2 aliases gx0's buffer — safe: gemm2 chunk k writes only after the
// causal chain prog1>=128(k+1) => rec1 consumed gx1[k] => gemm1[k] done =>
// prog0>=128(k+1) => rec0 finished reading gx0[k].
// ---------------------------------------------------------------------------
__global__ __launch_bounds__(256, 1) void mega_kernel(
    const float* __restrict__ whh, const float* __restrict__ wih,
    const float* __restrict__ bih, const float* __restrict__ bhh,
    float* __restrict__ gx0, float* __restrict__ gx1, float* __restrict__ gx2,
    int* __restrict__ syn)
{
    extern __shared__ char smraw[];
    const size_t WSZ = (size_t)GATES * HID;
    int* prog0  = syn;
    int* prog1  = syn + 64;
    int* ctrA   = syn + 128;
    int* ctrB   = syn + 129;
    int* chunk1 = syn + 130;
    int* chunk2 = chunk1 + BATCH * NCHUNK;

    const int bx = blockIdx.x;
    if (bx < BATCH) {
        rec_body(whh, gx0, g_h0, prog0, nullptr, bx, smraw);
        __syncthreads();
        rec_body(whh + 2 * WSZ, gx2, g_h2, nullptr, chunk2, bx, smraw);
    } else if (bx < 2 * BATCH) {
        rec_body(whh + WSZ, gx1, g_h1, prog1, chunk1, bx - BATCH, smraw);
        __syncthreads();
        gemm_worker(wih + WSZ, bih + GATES, bhh + GATES, gx1, g_h0,
                    prog0, ctrA, chunk1, smraw);
        __syncthreads();
        gemm_worker(wih + 2 * WSZ, bih + 2 * GATES, bhh + 2 * GATES, gx2, g_h1,
                    prog1, ctrB, chunk2, smraw);
    } else {
        gemm_worker(wih + WSZ, bih + GATES, bhh + GATES, gx1, g_h0,
                    prog0, ctrA, chunk1, smraw);
        __syncthreads();
        gemm_worker(wih + 2 * WSZ, bih + 2 * GATES, bhh + 2 * GATES, gx2, g_h1,
                    prog1, ctrB, chunk2, smraw);
    }
}

// ---------------------------------------------------------------------------
// MLP head: 64 CTAs, one per batch row. h_last[128] -> 64 -> 32 -> 10.
// ---------------------------------------------------------------------------
__global__ __launch_bounds__(256) void mlp_kernel(
    const float* __restrict__ w1, const float* __restrict__ b1,
    const float* __restrict__ w2, const float* __restrict__ b2,
    const float* __restrict__ w3, const float* __restrict__ b3,
    float* __restrict__ out)
{
    __shared__ float hs[128];
    __shared__ float y1[64];
    __shared__ float y2[32];

    const int tid = threadIdx.x;
    const int b   = blockIdx.x;
    if (tid < 128)
        hs[tid] = g_h2[(size_t)b * T_STEPS * HID + (size_t)(T_STEPS - 1) * HID + tid];
    __syncthreads();
    if (tid < 64) {
        float s = b1[tid];
        const float* wr = w1 + tid * 128;
#pragma unroll 16
        for (int k = 0; k < 128; k++) s = fmaf(hs[k], wr[k], s);
        y1[tid] = s;
    }
    __syncthreads();
    if (tid < 32) {
        float s = b2[tid];
        const float* wr = w2 + tid * 64;
#pragma unroll 16
        for (int k = 0; k < 64; k++) s = fmaf(y1[k], wr[k], s);
        y2[tid] = s;
    }
    __syncthreads();
    if (tid < 10) {
        float s = b3[tid];
        const float* wr = w3 + tid * 32;
#pragma unroll
        for (int k = 0; k < 32; k++) s = fmaf(y2[k], wr[k], s);
        out[b * 10 + tid] = s;
    }
}

// ---------------------------------------------------------------------------
extern "C" void kernel_launch(void* const* d_in, const int* in_sizes, int n_in,
                              void* d_out, int out_size)
{
    (void)in_sizes; (void)n_in; (void)out_size;
    const float* x   = (const float*)d_in[0];
    const float* wih = (const float*)d_in[1];
    const float* whh = (const float*)d_in[2];
    const float* bih = (const float*)d_in[3];
    const float* bhh = (const float*)d_in[4];
    const float* w1  = (const float*)d_in[5];
    const float* b1  = (const float*)d_in[6];
    const float* w2  = (const float*)d_in[7];
    const float* b2  = (const float*)d_in[8];
    const float* w3  = (const float*)d_in[9];
    const float* b3  = (const float*)d_in[10];

    void *pA = nullptr, *pB = nullptr, *pS = nullptr;
    cudaGetSymbolAddress(&pA, g_gxA);
    cudaGetSymbolAddress(&pB, g_gxB);
    cudaGetSymbolAddress(&pS, g_syn);
    float* bufA = (float*)pA;   // gx0, then gx2
    float* bufB = (float*)pB;   // gx1
    int*   syn  = (int*)pS;

    const int GEMM_SMEM = 4 * 128 * SR * 2 + 128 * 4;   // 139,776 B
    cudaFuncSetAttribute(gemm0_kernel, cudaFuncAttributeMaxDynamicSharedMemorySize, GEMM_SMEM);
    cudaFuncSetAttribute(mega_kernel,  cudaFuncAttributeMaxDynamicSharedMemorySize, GEMM_SMEM);

    cudaMemsetAsync(syn, 0, (130 + 2 * BATCH * NCHUNK) * sizeof(int));

    // gx0 = x @ wih0^T + biases  -> bufA
    gemm0_kernel<<<dim3(BATCH * T_STEPS / 128, 4), 256, GEMM_SMEM>>>(
        x, wih, bih, bhh);

    // All three rec layers + both inner GEMMs, pipelined per 128-step chunk.
    mega_kernel<<<NSM, 256, GEMM_SMEM>>>(whh, wih, bih, bhh,
                                         bufA, bufB, bufA, syn);

    mlp_kernel<<<BATCH, 256>>>(w1, b1, w2, b2, w3, b3, (float*)d_out);
}

// round 14
// speedup vs baseline: 1.3419x; 1.0034x over previous
#include <cuda_runtime.h>
#include <cuda_bf16.h>
#include <cstddef>

#define T_STEPS 2048
#define BATCH   64
#define HID     128
#define GATES   512          // 4*HID
#define RK      96           // k-values in registers (as pairs)
#define RKP     (RK/2)       // 48 register pairs
#define SK      (HID - RK)   // 32 k-values in smem
#define SKP     (SK/2)       // 16 smem pairs
#define NSM     148
#define NCHUNK  16           // 2048 / 128
#define CHSTEP  128

typedef unsigned long long ull;

// ---- packed fp32x2 helpers (sm_100+) --------------------------------------
__device__ __forceinline__ ull ffma2(ull a, ull b, ull c) {
    ull d;
    asm("fma.rn.f32x2 %0, %1, %2, %3;" : "=l"(d) : "l"(a), "l"(b), "l"(c));
    return d;
}
__device__ __forceinline__ ull pack2(float lo, float hi) {
    ull r; asm("mov.b64 %0, {%1, %2};" : "=l"(r) : "f"(lo), "f"(hi)); return r;
}
__device__ __forceinline__ float2 unpack2(ull v) {
    float2 f; asm("mov.b64 {%0, %1}, %2;" : "=f"(f.x), "=f"(f.y) : "l"(v)); return f;
}
__device__ __forceinline__ int ld_acquire_gpu(const int* p) {
    int v;
    asm volatile("ld.acquire.gpu.global.s32 %0, [%1];" : "=r"(v) : "l"(p) : "memory");
    return v;
}

// Scratch (device globals; no allocations allowed)
__device__ float g_gxA[(size_t)BATCH * T_STEPS * GATES];  // gx0, then reused for gx2
__device__ float g_gxB[(size_t)BATCH * T_STEPS * GATES];  // gx1
__device__ float g_h0 [(size_t)BATCH * T_STEPS * HID];
__device__ float g_h1 [(size_t)BATCH * T_STEPS * HID];
__device__ float g_h2 [(size_t)BATCH * T_STEPS * HID];
__device__ int   g_syn[130 + BATCH * NCHUNK * 2];  // prog0[64] prog1[64] ctrA ctrB chunk1 chunk2

// ---------------------------------------------------------------------------
// GEMM tile machinery (bf16 3-product split, fp32 acc, ldmatrix)
// ---------------------------------------------------------------------------
#define SR 136   // padded bf16 row stride

__device__ __forceinline__ void mma_bf16(float* d, const unsigned* a, const unsigned* b) {
    asm volatile(
        "mma.sync.aligned.m16n8k16.row.col.f32.bf16.bf16.f32 "
        "{%0,%1,%2,%3}, {%4,%5,%6,%7}, {%8,%9}, {%0,%1,%2,%3};"
        : "+f"(d[0]), "+f"(d[1]), "+f"(d[2]), "+f"(d[3])
        : "r"(a[0]), "r"(a[1]), "r"(a[2]), "r"(a[3]), "r"(b[0]), "r"(b[1]));
}
__device__ __forceinline__ void ldsm_x4(unsigned* r, unsigned addr) {
    asm volatile("ldmatrix.sync.aligned.m8n8.x4.shared.b16 {%0,%1,%2,%3}, [%4];"
                 : "=r"(r[0]), "=r"(r[1]), "=r"(r[2]), "=r"(r[3]) : "r"(addr));
}

__device__ void gemm_tile(const float* __restrict__ A, const float* __restrict__ W,
                          const float* __restrict__ bih, const float* __restrict__ bhh,
                          float* __restrict__ out, int brow, int bcol, char* gsm)
{
    __nv_bfloat16* a_hi = (__nv_bfloat16*)gsm;                  // [128][SR]
    __nv_bfloat16* a_lo = a_hi + 128 * SR;
    __nv_bfloat16* w_hi = a_lo + 128 * SR;
    __nv_bfloat16* w_lo = w_hi + 128 * SR;
    float*         bias_s = (float*)(w_lo + 128 * SR);          // [128]

    const int tid = threadIdx.x;
    if (tid < 128) bias_s[tid] = bih[bcol + tid] + bhh[bcol + tid];

    {
        const int row = tid >> 1;
        const int cb  = (tid & 1) * 64;
        const float* Ar = A + (size_t)(brow + row) * HID + cb;
        const float* Wr = W + (size_t)(bcol + row) * HID + cb;
        __nv_bfloat16* ah = a_hi + row * SR + cb;
        __nv_bfloat16* al = a_lo + row * SR + cb;
        __nv_bfloat16* wh = w_hi + row * SR + cb;
        __nv_bfloat16* wl = w_lo + row * SR + cb;
#pragma unroll 4
        for (int c = 0; c < 64; c += 4) {
            float4 v = *(const float4*)(Ar + c);
            __nv_bfloat16 hx = __float2bfloat16_rn(v.x);
            __nv_bfloat16 hy = __float2bfloat16_rn(v.y);
            __nv_bfloat16 hz = __float2bfloat16_rn(v.z);
            __nv_bfloat16 hw = __float2bfloat16_rn(v.w);
            __nv_bfloat162 H0; H0.x = hx; H0.y = hy;
            __nv_bfloat162 H1; H1.x = hz; H1.y = hw;
            __nv_bfloat162 L0 = __floats2bfloat162_rn(v.x - __bfloat162float(hx),
                                                      v.y - __bfloat162float(hy));
            __nv_bfloat162 L1 = __floats2bfloat162_rn(v.z - __bfloat162float(hz),
                                                      v.w - __bfloat162float(hw));
            *(__nv_bfloat162*)(ah + c)     = H0;
            *(__nv_bfloat162*)(ah + c + 2) = H1;
            *(__nv_bfloat162*)(al + c)     = L0;
            *(__nv_bfloat162*)(al + c + 2) = L1;

            float4 u = *(const float4*)(Wr + c);
            __nv_bfloat16 gx = __float2bfloat16_rn(u.x);
            __nv_bfloat16 gy = __float2bfloat16_rn(u.y);
            __nv_bfloat16 gz = __float2bfloat16_rn(u.z);
            __nv_bfloat16 gw = __float2bfloat16_rn(u.w);
            __nv_bfloat162 G0; G0.x = gx; G0.y = gy;
            __nv_bfloat162 G1; G1.x = gz; G1.y = gw;
            __nv_bfloat162 M0 = __floats2bfloat162_rn(u.x - __bfloat162float(gx),
                                                      u.y - __bfloat162float(gy));
            __nv_bfloat162 M1 = __floats2bfloat162_rn(u.z - __bfloat162float(gz),
                                                      u.w - __bfloat162float(gw));
            *(__nv_bfloat162*)(wh + c)     = G0;
            *(__nv_bfloat162*)(wh + c + 2) = G1;
            *(__nv_bfloat162*)(wl + c)     = M0;
            *(__nv_bfloat162*)(wl + c + 2) = M1;
        }
    }
    __syncthreads();

    const int wid    = tid >> 5;
    const int lane   = tid & 31;
    const int warp_m = wid >> 1;
    const int warp_n = wid & 1;
    const int m_base = warp_m * 32;
    const int n_base = warp_n * 64;

    const unsigned a_hi_s = (unsigned)__cvta_generic_to_shared(a_hi);
    const unsigned a_lo_s = (unsigned)__cvta_generic_to_shared(a_lo);
    const unsigned w_hi_s = (unsigned)__cvta_generic_to_shared(w_hi);
    const unsigned w_lo_s = (unsigned)__cvta_generic_to_shared(w_lo);

    const int arow  = m_base + (lane & 15);
    const int akoff = (lane >> 4) * 8;
    const int gsel  = lane >> 3;
    const int brow_ = n_base + ((gsel >> 1) & 1) * 8 + (lane & 7);
    const int bkoff = (gsel & 1) * 8;

    float d[2][8][4];
#pragma unroll
    for (int mi = 0; mi < 2; mi++)
#pragma unroll
        for (int ni = 0; ni < 8; ni++)
#pragma unroll
            for (int e = 0; e < 4; e++) d[mi][ni][e] = 0.f;

#pragma unroll
    for (int k0 = 0; k0 < HID; k0 += 16) {
        unsigned ah[2][4], al[2][4];
#pragma unroll
        for (int mi = 0; mi < 2; mi++) {
            unsigned off = (unsigned)(((arow + mi * 16) * SR + akoff + k0) * 2);
            ldsm_x4(ah[mi], a_hi_s + off);
            ldsm_x4(al[mi], a_lo_s + off);
        }
        unsigned bh[4][4], bl[4][4];
#pragma unroll
        for (int nb = 0; nb < 4; nb++) {
            unsigned off = (unsigned)(((brow_ + nb * 16) * SR + bkoff + k0) * 2);
            ldsm_x4(bh[nb], w_hi_s + off);
            ldsm_x4(bl[nb], w_lo_s + off);
        }
        // Pass 1: hi*hi — 16 independent accumulators, no chains
#pragma unroll
        for (int mi = 0; mi < 2; mi++)
#pragma unroll
            for (int nb = 0; nb < 4; nb++) {
                mma_bf16(d[mi][2 * nb],     ah[mi], &bh[nb][0]);
                mma_bf16(d[mi][2 * nb + 1], ah[mi], &bh[nb][2]);
            }
        // Pass 2: hi*lo
#pragma unroll
        for (int mi = 0; mi < 2; mi++)
#pragma unroll
            for (int nb = 0; nb < 4; nb++) {
                mma_bf16(d[mi][2 * nb],     ah[mi], &bl[nb][0]);
                mma_bf16(d[mi][2 * nb + 1], ah[mi], &bl[nb][2]);
            }
        // Pass 3: lo*hi
#pragma unroll
        for (int mi = 0; mi < 2; mi++)
#pragma unroll
            for (int nb = 0; nb < 4; nb++) {
                mma_bf16(d[mi][2 * nb],     al[mi], &bh[nb][0]);
                mma_bf16(d[mi][2 * nb + 1], al[mi], &bh[nb][2]);
            }
    }

    const int tr = lane >> 2;
    const int tc = (lane & 3) * 2;
#pragma unroll
    for (int mi = 0; mi < 2; mi++) {
        int gr0 = brow + m_base + mi * 16 + tr;
#pragma unroll
        for (int ni = 0; ni < 8; ni++) {
            int lc = n_base + ni * 8 + tc;
            float2 bv = *(const float2*)&bias_s[lc];
            float2 o0 = {d[mi][ni][0] + bv.x, d[mi][ni][1] + bv.y};
            float2 o1 = {d[mi][ni][2] + bv.x, d[mi][ni][3] + bv.y};
            *(float2*)(out + (size_t)gr0 * GATES + bcol + lc)       = o0;
            *(float2*)(out + (size_t)(gr0 + 8) * GATES + bcol + lc) = o1;
        }
    }
}

// Standalone layer-0 GEMM over the whole input
__global__ __launch_bounds__(256) void gemm0_kernel(
    const float* __restrict__ A, const float* __restrict__ W,
    const float* __restrict__ bih, const float* __restrict__ bhh)
{
    extern __shared__ char gsm[];
    gemm_tile(A, W, bih, bhh, g_gxA, blockIdx.x * 128, blockIdx.y * 128, gsm);
}

// ---------------------------------------------------------------------------
// Recurrence body (R3 structure, measured best). Optional:
//  - prog:       publish progress every 64 steps (h producer role)
//  - chunkready: gate gx consumption per 128-step chunk (4 tiles per chunk)
// ---------------------------------------------------------------------------
__device__ __forceinline__ float sigm(float x) {
    return __fdividef(1.f, 1.f + __expf(-x));
}
__device__ __forceinline__ float tanh_fast(float x) {
    float e = __expf(2.f * x);
    return 1.f - __fdividef(2.f, e + 1.f);
}

__device__ void rec_body(const float* __restrict__ whh, const float* __restrict__ gx,
                         float* __restrict__ hout, int* __restrict__ prog,
                         const int* __restrict__ chunkready, int b, char* smraw)
{
    ull*   ws2 = (ull*)smraw;                    // [SKP][512] pair-major weight pairs
    float* g_s = (float*)(ws2 + SKP * 512);      // 512 gate pre-activations
    float* h_s = g_s + GATES;                    // 128 hidden state

    const int tid = threadIdx.x;
    const int r0  = tid;
    const int r1  = tid + 256;

    ull wa2[RKP], wb2[RKP];
    {
        const ull* wp0 = (const ull*)(whh + (size_t)r0 * HID);
        const ull* wp1 = (const ull*)(whh + (size_t)r1 * HID);
#pragma unroll
        for (int q = 0; q < RKP; q++) { wa2[q] = wp0[q]; wb2[q] = wp1[q]; }
    }
    for (int idx = tid; idx < SKP * 512; idx += 256) {
        int r = idx & 511, p = idx >> 9;
        ws2[idx] = ((const ull*)(whh + (size_t)r * HID))[RKP + p];
    }
    if (tid < HID) h_s[tid] = 0.f;
    float c = 0.f;
    __syncthreads();

    const float* gxb = gx   + (size_t)b * T_STEPS * GATES;
    float*       hb  = hout + (size_t)b * T_STEPS * HID;

    float nga = 0.f, ngb = 0.f;
    if (!chunkready) { nga = gxb[r0]; ngb = gxb[r1]; }

    for (int t = 0; t < T_STEPS; t++) {
        if (chunkready && (t & (CHSTEP - 1)) == 0) {
            if (tid == 0) {
                const int* cw = chunkready + b * NCHUNK + (t >> 7);
                while (ld_acquire_gpu(cw) < 4) __nanosleep(128);
            }
            __syncthreads();
            nga = __ldg(gxb + (size_t)t * GATES + r0);
            ngb = __ldg(gxb + (size_t)t * GATES + r1);
        }
        ull acc0 = pack2(nga, 0.f);
        ull acc1 = pack2(ngb, 0.f);
        if (t + 1 < T_STEPS && (!chunkready || ((t + 1) & (CHSTEP - 1)) != 0)) {
            nga = __ldg(gxb + (size_t)(t + 1) * GATES + r0);
            ngb = __ldg(gxb + (size_t)(t + 1) * GATES + r1);
        }
        const ull* h2 = (const ull*)h_s;   // 64 packed h pairs (broadcast LDS.64)
#pragma unroll
        for (int q = 0; q < RKP; q++) {
            ull hp = h2[q];
            acc0 = ffma2(hp, wa2[q], acc0);
            acc1 = ffma2(hp, wb2[q], acc1);
        }
#pragma unroll
        for (int p = 0; p < SKP; p++) {
            ull hp = h2[RKP + p];
            acc0 = ffma2(hp, ws2[p * 512 + r0], acc0);
            acc1 = ffma2(hp, ws2[p * 512 + r1], acc1);
        }
        float2 v0 = unpack2(acc0);
        float2 v1 = unpack2(acc1);
        g_s[r0] = v0.x + v0.y;
        g_s[r1] = v1.x + v1.y;
        __syncthreads();
        if (tid < 128) {
            float i_ = sigm(g_s[tid]);
            float f_ = sigm(g_s[tid + 128]);
            float g_ = tanh_fast(g_s[tid + 256]);
            float o_ = sigm(g_s[tid + 384]);
            c = fmaf(f_, c, i_ * g_);
            float hv = o_ * tanh_fast(c);
            h_s[tid] = hv;
            hb[(size_t)t * HID + tid] = hv;
        }
        bool pub = prog && ((t & 63) == 63);
        if (pub) __threadfence();          // all threads: release h writes
        __syncthreads();
        if (pub && tid == 0) atomicExch(prog + b, t + 1);
    }
}

// ---------------------------------------------------------------------------
// GEMM worker: pulls 128x128 tiles from an atomic pool (chunk-major order),
// paced by producer progress (prog). Publishes per-(b,chunk) counters.
// ---------------------------------------------------------------------------
__device__ void gemm_worker(const float* __restrict__ W,
                            const float* __restrict__ bih, const float* __restrict__ bhh,
                            float* __restrict__ out, const float* __restrict__ hsrc,
                            int* __restrict__ prog, int* __restrict__ ctr,
                            int* __restrict__ chunkdone, char* gsm)
{
    const int tid = threadIdx.x;
    __shared__ int s_idx;
    const int NT = NCHUNK * BATCH * 4;   // 4096 tiles
    while (true) {
        if (tid == 0) s_idx = atomicAdd(ctr, 1);
        __syncthreads();
        int idx = s_idx;
        __syncthreads();
        if (idx >= NT) break;
        int chunk = idx >> 8;            // 0..15
        int b     = (idx >> 2) & 63;
        int cy    = idx & 3;
        if (tid == 0) {
            int need = (chunk + 1) * CHSTEP;
            int v;
            while (true) {
                asm volatile("ld.global.cg.u32 %0, [%1];" : "=r"(v) : "l"(prog + b));
                if (v >= need) break;
                __nanosleep(256);
            }
            __threadfence();
        }
        __syncthreads();
        gemm_tile(hsrc, W, bih, bhh, out, b * T_STEPS + chunk * CHSTEP, cy * 128, gsm);
        __threadfence();                 // all threads: release tile stores
        __syncthreads();
        if (tid == 0) atomicAdd(chunkdone + b * NCHUNK + chunk, 1);
    }
}

// ---------------------------------------------------------------------------
// Mega kernel: all three rec layers pipelined in one launch.
//  blocks [0,64):    rec0 (publishes prog0) then rec2 (gated on chunk2)
//  blocks [64,128):  rec1 (gated on chunk1, publishes prog1), then gemm pools
//  blocks [128,148): gemm1 pool (h0->gx1), then gemm2 pool (h1->gx2)
// gx2 aliases gx0's buffer — safe: gemm2 chunk k writes only after the
// causal chain prog1>=128(k+1) => rec1 consumed gx1[k] => gemm1[k] done =>
// prog0>=128(k+1) => rec0 finished reading gx0[k].
// ---------------------------------------------------------------------------
__global__ __launch_bounds__(256, 1) void mega_kernel(
    const float* __restrict__ whh, const float* __restrict__ wih,
    const float* __restrict__ bih, const float* __restrict__ bhh,
    float* __restrict__ gx0, float* __restrict__ gx1, float* __restrict__ gx2,
    int* __restrict__ syn)
{
    extern __shared__ char smraw[];
    const size_t WSZ = (size_t)GATES * HID;
    int* prog0  = syn;
    int* prog1  = syn + 64;
    int* ctrA   = syn + 128;
    int* ctrB   = syn + 129;
    int* chunk1 = syn + 130;
    int* chunk2 = chunk1 + BATCH * NCHUNK;

    const int bx = blockIdx.x;
    if (bx < BATCH) {
        rec_body(whh, gx0, g_h0, prog0, nullptr, bx, smraw);
        __syncthreads();
        rec_body(whh + 2 * WSZ, gx2, g_h2, nullptr, chunk2, bx, smraw);
    } else if (bx < 2 * BATCH) {
        rec_body(whh + WSZ, gx1, g_h1, prog1, chunk1, bx - BATCH, smraw);
        __syncthreads();
        gemm_worker(wih + WSZ, bih + GATES, bhh + GATES, gx1, g_h0,
                    prog0, ctrA, chunk1, smraw);
        __syncthreads();
        gemm_worker(wih + 2 * WSZ, bih + 2 * GATES, bhh + 2 * GATES, gx2, g_h1,
                    prog1, ctrB, chunk2, smraw);
    } else {
        gemm_worker(wih + WSZ, bih + GATES, bhh + GATES, gx1, g_h0,
                    prog0, ctrA, chunk1, smraw);
        __syncthreads();
        gemm_worker(wih + 2 * WSZ, bih + 2 * GATES, bhh + 2 * GATES, gx2, g_h1,
                    prog1, ctrB, chunk2, smraw);
    }
}

// ---------------------------------------------------------------------------
// MLP head: 64 CTAs, one per batch row. h_last[128] -> 64 -> 32 -> 10.
// ---------------------------------------------------------------------------
__global__ __launch_bounds__(256) void mlp_kernel(
    const float* __restrict__ w1, const float* __restrict__ b1,
    const float* __restrict__ w2, const float* __restrict__ b2,
    const float* __restrict__ w3, const float* __restrict__ b3,
    float* __restrict__ out)
{
    __shared__ float hs[128];
    __shared__ float y1[64];
    __shared__ float y2[32];

    const int tid = threadIdx.x;
    const int b   = blockIdx.x;
    if (tid < 128)
        hs[tid] = g_h2[(size_t)b * T_STEPS * HID + (size_t)(T_STEPS - 1) * HID + tid];
    __syncthreads();
    if (tid < 64) {
        float s = b1[tid];
        const float* wr = w1 + tid * 128;
#pragma unroll 16
        for (int k = 0; k < 128; k++) s = fmaf(hs[k], wr[k], s);
        y1[tid] = s;
    }
    __syncthreads();
    if (tid < 32) {
        float s = b2[tid];
        const float* wr = w2 + tid * 64;
#pragma unroll 16
        for (int k = 0; k < 64; k++) s = fmaf(y1[k], wr[k], s);
        y2[tid] = s;
    }
    __syncthreads();
    if (tid < 10) {
        float s = b3[tid];
        const float* wr = w3 + tid * 32;
#pragma unroll
        for (int k = 0; k < 32; k++) s = fmaf(y2[k], wr[k], s);
        out[b * 10 + tid] = s;
    }
}

// ---------------------------------------------------------------------------
extern "C" void kernel_launch(void* const* d_in, const int* in_sizes, int n_in,
                              void* d_out, int out_size)
{
    (void)in_sizes; (void)n_in; (void)out_size;
    const float* x   = (const float*)d_in[0];
    const float* wih = (const float*)d_in[1];
    const float* whh = (const float*)d_in[2];
    const float* bih = (const float*)d_in[3];
    const float* bhh = (const float*)d_in[4];
    const float* w1  = (const float*)d_in[5];
    const float* b1  = (const float*)d_in[6];
    const float* w2  = (const float*)d_in[7];
    const float* b2  = (const float*)d_in[8];
    const float* w3  = (const float*)d_in[9];
    const float* b3  = (const float*)d_in[10];

    void *pA = nullptr, *pB = nullptr, *pS = nullptr;
    cudaGetSymbolAddress(&pA, g_gxA);
    cudaGetSymbolAddress(&pB, g_gxB);
    cudaGetSymbolAddress(&pS, g_syn);
    float* bufA = (float*)pA;   // gx0, then gx2
    float* bufB = (float*)pB;   // gx1
    int*   syn  = (int*)pS;

    const int GEMM_SMEM = 4 * 128 * SR * 2 + 128 * 4;   // 139,776 B
    cudaFuncSetAttribute(gemm0_kernel, cudaFuncAttributeMaxDynamicSharedMemorySize, GEMM_SMEM);
    cudaFuncSetAttribute(mega_kernel,  cudaFuncAttributeMaxDynamicSharedMemorySize, GEMM_SMEM);

    cudaMemsetAsync(syn, 0, (130 + 2 * BATCH * NCHUNK) * sizeof(int));

    // gx0 = x @ wih0^T + biases  -> bufA
    gemm0_kernel<<<dim3(BATCH * T_STEPS / 128, 4), 256, GEMM_SMEM>>>(
        x, wih, bih, bhh);

    // All three rec layers + both inner GEMMs, pipelined per 128-step chunk.
    mega_kernel<<<NSM, 256, GEMM_SMEM>>>(whh, wih, bih, bhh,
                                         bufA, bufB, bufA, syn);

    mlp_kernel<<<BATCH, 256>>>(w1, b1, w2, b2, w3, b3, (float*)d_out);
}

// round 15
// speedup vs baseline: 1.4005x; 1.0437x over previous
#include <cuda_runtime.h>
#include <cuda_bf16.h>
#include <cstddef>

#define T_STEPS 2048
#define BATCH   64
#define HID     128
#define GATES   512          // 4*HID
#define RK      96           // k-values in registers (as pairs)
#define RKP     (RK/2)       // 48 register pairs
#define SK      (HID - RK)   // 32 k-values in smem
#define SKP     (SK/2)       // 16 smem pairs
#define NSM     148
#define NCHUNK  16           // 2048 / 128
#define CHSTEP  128

typedef unsigned long long ull;

// ---- packed fp32x2 helpers (sm_100+) --------------------------------------
__device__ __forceinline__ ull ffma2(ull a, ull b, ull c) {
    ull d;
    asm("fma.rn.f32x2 %0, %1, %2, %3;" : "=l"(d) : "l"(a), "l"(b), "l"(c));
    return d;
}
__device__ __forceinline__ ull pack2(float lo, float hi) {
    ull r; asm("mov.b64 %0, {%1, %2};" : "=l"(r) : "f"(lo), "f"(hi)); return r;
}
__device__ __forceinline__ float2 unpack2(ull v) {
    float2 f; asm("mov.b64 {%0, %1}, %2;" : "=f"(f.x), "=f"(f.y) : "l"(v)); return f;
}
__device__ __forceinline__ int ld_acquire_gpu(const int* p) {
    int v;
    asm volatile("ld.acquire.gpu.global.s32 %0, [%1];" : "=r"(v) : "l"(p) : "memory");
    return v;
}

// Scratch (device globals; no allocations allowed)
__device__ float g_gxA[(size_t)BATCH * T_STEPS * GATES];  // gx0, then reused for gx2
__device__ float g_gxB[(size_t)BATCH * T_STEPS * GATES];  // gx1
__device__ __nv_bfloat16 g_xhi[(size_t)BATCH * T_STEPS * HID];  // x split
__device__ __nv_bfloat16 g_xlo[(size_t)BATCH * T_STEPS * HID];
__device__ __nv_bfloat16 g_h0hi[(size_t)BATCH * T_STEPS * HID]; // h0 split
__device__ __nv_bfloat16 g_h0lo[(size_t)BATCH * T_STEPS * HID];
__device__ __nv_bfloat16 g_h1hi[(size_t)BATCH * T_STEPS * HID]; // h1 split
__device__ __nv_bfloat16 g_h1lo[(size_t)BATCH * T_STEPS * HID];
__device__ __nv_bfloat16 g_whi[3 * GATES * HID];                // wih split (3 layers)
__device__ __nv_bfloat16 g_wlo[3 * GATES * HID];
__device__ float g_h2last[BATCH * HID];
__device__ int   g_syn[130 + BATCH * NCHUNK * 2];  // prog0[64] prog1[64] ctrA ctrB chunk1 chunk2

// ---------------------------------------------------------------------------
// fp32 -> (bf16 hi, bf16 lo) splitter, vectorized 4 elements/thread
// ---------------------------------------------------------------------------
__global__ __launch_bounds__(256) void split_kernel(
    const float* __restrict__ src, __nv_bfloat16* __restrict__ hi,
    __nv_bfloat16* __restrict__ lo, long n4)
{
    long i = (long)blockIdx.x * 256 + threadIdx.x;
    if (i >= n4) return;
    float4 v = ((const float4*)src)[i];
    __nv_bfloat16 h0 = __float2bfloat16_rn(v.x);
    __nv_bfloat16 h1 = __float2bfloat16_rn(v.y);
    __nv_bfloat16 h2 = __float2bfloat16_rn(v.z);
    __nv_bfloat16 h3 = __float2bfloat16_rn(v.w);
    __nv_bfloat162 H0; H0.x = h0; H0.y = h1;
    __nv_bfloat162 H1; H1.x = h2; H1.y = h3;
    __nv_bfloat162 L0 = __floats2bfloat162_rn(v.x - __bfloat162float(h0),
                                              v.y - __bfloat162float(h1));
    __nv_bfloat162 L1 = __floats2bfloat162_rn(v.z - __bfloat162float(h2),
                                              v.w - __bfloat162float(h3));
    ((__nv_bfloat162*)hi)[2 * i]     = H0;
    ((__nv_bfloat162*)hi)[2 * i + 1] = H1;
    ((__nv_bfloat162*)lo)[2 * i]     = L0;
    ((__nv_bfloat162*)lo)[2 * i + 1] = L1;
}

// ---------------------------------------------------------------------------
// GEMM tile (pre-split bf16 inputs, fp32 acc, ldmatrix). Load phase is pure
// vector copy gmem->smem — no conversion.
// ---------------------------------------------------------------------------
#define SR 136   // padded bf16 row stride

__device__ __forceinline__ void mma_bf16(float* d, const unsigned* a, const unsigned* b) {
    asm volatile(
        "mma.sync.aligned.m16n8k16.row.col.f32.bf16.bf16.f32 "
        "{%0,%1,%2,%3}, {%4,%5,%6,%7}, {%8,%9}, {%0,%1,%2,%3};"
        : "+f"(d[0]), "+f"(d[1]), "+f"(d[2]), "+f"(d[3])
        : "r"(a[0]), "r"(a[1]), "r"(a[2]), "r"(a[3]), "r"(b[0]), "r"(b[1]));
}
__device__ __forceinline__ void ldsm_x4(unsigned* r, unsigned addr) {
    asm volatile("ldmatrix.sync.aligned.m8n8.x4.shared.b16 {%0,%1,%2,%3}, [%4];"
                 : "=r"(r[0]), "=r"(r[1]), "=r"(r[2]), "=r"(r[3]) : "r"(addr));
}

__device__ void gemm_tile(const __nv_bfloat16* __restrict__ Ahi,
                          const __nv_bfloat16* __restrict__ Alo,
                          const __nv_bfloat16* __restrict__ Whi,
                          const __nv_bfloat16* __restrict__ Wlo,
                          const float* __restrict__ bih, const float* __restrict__ bhh,
                          float* __restrict__ out, int brow, int bcol, char* gsm)
{
    __nv_bfloat16* a_hi = (__nv_bfloat16*)gsm;                  // [128][SR]
    __nv_bfloat16* a_lo = a_hi + 128 * SR;
    __nv_bfloat16* w_hi = a_lo + 128 * SR;
    __nv_bfloat16* w_lo = w_hi + 128 * SR;
    float*         bias_s = (float*)(w_lo + 128 * SR);          // [128]

    const int tid = threadIdx.x;
    if (tid < 128) bias_s[tid] = bih[bcol + tid] + bhh[bcol + tid];

    // ---- pure copy phase: 4 x 128B per thread ----
    {
        const int row = tid >> 1;
        const int cb  = (tid & 1) * 64;
        const uint4* sAh = (const uint4*)(Ahi + (size_t)(brow + row) * HID + cb);
        const uint4* sAl = (const uint4*)(Alo + (size_t)(brow + row) * HID + cb);
        const uint4* sWh = (const uint4*)(Whi + (size_t)(bcol + row) * HID + cb);
        const uint4* sWl = (const uint4*)(Wlo + (size_t)(bcol + row) * HID + cb);
        uint4* dAh = (uint4*)(a_hi + row * SR + cb);
        uint4* dAl = (uint4*)(a_lo + row * SR + cb);
        uint4* dWh = (uint4*)(w_hi + row * SR + cb);
        uint4* dWl = (uint4*)(w_lo + row * SR + cb);
#pragma unroll
        for (int i = 0; i < 8; i++) {
            dAh[i] = sAh[i];
            dAl[i] = sAl[i];
            dWh[i] = sWh[i];
            dWl[i] = sWl[i];
        }
    }
    __syncthreads();

    const int wid    = tid >> 5;
    const int lane   = tid & 31;
    const int warp_m = wid >> 1;
    const int warp_n = wid & 1;
    const int m_base = warp_m * 32;
    const int n_base = warp_n * 64;

    const unsigned a_hi_s = (unsigned)__cvta_generic_to_shared(a_hi);
    const unsigned a_lo_s = (unsigned)__cvta_generic_to_shared(a_lo);
    const unsigned w_hi_s = (unsigned)__cvta_generic_to_shared(w_hi);
    const unsigned w_lo_s = (unsigned)__cvta_generic_to_shared(w_lo);

    const int arow  = m_base + (lane & 15);
    const int akoff = (lane >> 4) * 8;
    const int gsel  = lane >> 3;
    const int brow_ = n_base + ((gsel >> 1) & 1) * 8 + (lane & 7);
    const int bkoff = (gsel & 1) * 8;

    float d[2][8][4];
#pragma unroll
    for (int mi = 0; mi < 2; mi++)
#pragma unroll
        for (int ni = 0; ni < 8; ni++)
#pragma unroll
            for (int e = 0; e < 4; e++) d[mi][ni][e] = 0.f;

#pragma unroll
    for (int k0 = 0; k0 < HID; k0 += 16) {
        unsigned ah[2][4], al[2][4];
#pragma unroll
        for (int mi = 0; mi < 2; mi++) {
            unsigned off = (unsigned)(((arow + mi * 16) * SR + akoff + k0) * 2);
            ldsm_x4(ah[mi], a_hi_s + off);
            ldsm_x4(al[mi], a_lo_s + off);
        }
        unsigned bh[4][4], bl[4][4];
#pragma unroll
        for (int nb = 0; nb < 4; nb++) {
            unsigned off = (unsigned)(((brow_ + nb * 16) * SR + bkoff + k0) * 2);
            ldsm_x4(bh[nb], w_hi_s + off);
            ldsm_x4(bl[nb], w_lo_s + off);
        }
#pragma unroll
        for (int mi = 0; mi < 2; mi++)
#pragma unroll
            for (int nb = 0; nb < 4; nb++) {
                mma_bf16(d[mi][2 * nb],     ah[mi], &bh[nb][0]);
                mma_bf16(d[mi][2 * nb],     ah[mi], &bl[nb][0]);
                mma_bf16(d[mi][2 * nb],     al[mi], &bh[nb][0]);
                mma_bf16(d[mi][2 * nb + 1], ah[mi], &bh[nb][2]);
                mma_bf16(d[mi][2 * nb + 1], ah[mi], &bl[nb][2]);
                mma_bf16(d[mi][2 * nb + 1], al[mi], &bh[nb][2]);
            }
    }

    const int tr = lane >> 2;
    const int tc = (lane & 3) * 2;
#pragma unroll
    for (int mi = 0; mi < 2; mi++) {
        int gr0 = brow + m_base + mi * 16 + tr;
#pragma unroll
        for (int ni = 0; ni < 8; ni++) {
            int lc = n_base + ni * 8 + tc;
            float2 bv = *(const float2*)&bias_s[lc];
            float2 o0 = {d[mi][ni][0] + bv.x, d[mi][ni][1] + bv.y};
            float2 o1 = {d[mi][ni][2] + bv.x, d[mi][ni][3] + bv.y};
            *(float2*)(out + (size_t)gr0 * GATES + bcol + lc)       = o0;
            *(float2*)(out + (size_t)(gr0 + 8) * GATES + bcol + lc) = o1;
        }
    }
}

// Standalone layer-0 GEMM over the whole (pre-split) input
__global__ __launch_bounds__(256) void gemm0_kernel(
    const float* __restrict__ bih, const float* __restrict__ bhh)
{
    extern __shared__ char gsm[];
    gemm_tile(g_xhi, g_xlo, g_whi, g_wlo, bih, bhh, g_gxA,
              blockIdx.x * 128, blockIdx.y * 128, gsm);
}

// ---------------------------------------------------------------------------
// Recurrence body (R3 structure, measured best).
//  - hhi/hlo: optional bf16 hi/lo h output (for next layer's GEMM)
//  - hlast:   optional fp32 final-step h output (for MLP)
//  - prog:    publish progress every 64 steps
//  - chunkready: gate gx consumption per 128-step chunk (4 tiles/chunk)
// ---------------------------------------------------------------------------
__device__ __forceinline__ float sigm(float x) {
    return __fdividef(1.f, 1.f + __expf(-x));
}
__device__ __forceinline__ float tanh_fast(float x) {
    float e = __expf(2.f * x);
    return 1.f - __fdividef(2.f, e + 1.f);
}

__device__ void rec_body(const float* __restrict__ whh, const float* __restrict__ gx,
                         __nv_bfloat16* __restrict__ hhi, __nv_bfloat16* __restrict__ hlo,
                         float* __restrict__ hlast,
                         int* __restrict__ prog, const int* __restrict__ chunkready,
                         int b, char* smraw)
{
    ull*   ws2 = (ull*)smraw;                    // [SKP][512] pair-major weight pairs
    float* g_s = (float*)(ws2 + SKP * 512);      // 512 gate pre-activations
    float* h_s = g_s + GATES;                    // 128 hidden state

    const int tid = threadIdx.x;
    const int r0  = tid;
    const int r1  = tid + 256;

    ull wa2[RKP], wb2[RKP];
    {
        const ull* wp0 = (const ull*)(whh + (size_t)r0 * HID);
        const ull* wp1 = (const ull*)(whh + (size_t)r1 * HID);
#pragma unroll
        for (int q = 0; q < RKP; q++) { wa2[q] = wp0[q]; wb2[q] = wp1[q]; }
    }
    for (int idx = tid; idx < SKP * 512; idx += 256) {
        int r = idx & 511, p = idx >> 9;
        ws2[idx] = ((const ull*)(whh + (size_t)r * HID))[RKP + p];
    }
    if (tid < HID) h_s[tid] = 0.f;
    float c = 0.f;
    __syncthreads();

    const float* gxb = gx + (size_t)b * T_STEPS * GATES;
    __nv_bfloat16* hhib = hhi ? hhi + (size_t)b * T_STEPS * HID : nullptr;
    __nv_bfloat16* hlob = hlo ? hlo + (size_t)b * T_STEPS * HID : nullptr;

    float nga = 0.f, ngb = 0.f;
    if (!chunkready) { nga = gxb[r0]; ngb = gxb[r1]; }

    for (int t = 0; t < T_STEPS; t++) {
        if (chunkready && (t & (CHSTEP - 1)) == 0) {
            if (tid == 0) {
                const int* cw = chunkready + b * NCHUNK + (t >> 7);
                while (ld_acquire_gpu(cw) < 4) __nanosleep(128);
            }
            __syncthreads();
            nga = __ldg(gxb + (size_t)t * GATES + r0);
            ngb = __ldg(gxb + (size_t)t * GATES + r1);
        }
        ull acc0 = pack2(nga, 0.f);
        ull acc1 = pack2(ngb, 0.f);
        if (t + 1 < T_STEPS && (!chunkready || ((t + 1) & (CHSTEP - 1)) != 0)) {
            nga = __ldg(gxb + (size_t)(t + 1) * GATES + r0);
            ngb = __ldg(gxb + (size_t)(t + 1) * GATES + r1);
        }
        const ull* h2 = (const ull*)h_s;   // 64 packed h pairs (broadcast LDS.64)
#pragma unroll
        for (int q = 0; q < RKP; q++) {
            ull hp = h2[q];
            acc0 = ffma2(hp, wa2[q], acc0);
            acc1 = ffma2(hp, wb2[q], acc1);
        }
#pragma unroll
        for (int p = 0; p < SKP; p++) {
            ull hp = h2[RKP + p];
            acc0 = ffma2(hp, ws2[p * 512 + r0], acc0);
            acc1 = ffma2(hp, ws2[p * 512 + r1], acc1);
        }
        float2 v0 = unpack2(acc0);
        float2 v1 = unpack2(acc1);
        g_s[r0] = v0.x + v0.y;
        g_s[r1] = v1.x + v1.y;
        __syncthreads();
        if (tid < 128) {
            float i_ = sigm(g_s[tid]);
            float f_ = sigm(g_s[tid + 128]);
            float g_ = tanh_fast(g_s[tid + 256]);
            float o_ = sigm(g_s[tid + 384]);
            c = fmaf(f_, c, i_ * g_);
            float hv = o_ * tanh_fast(c);
            h_s[tid] = hv;
            if (hhib) {
                __nv_bfloat16 hb16 = __float2bfloat16_rn(hv);
                hhib[(size_t)t * HID + tid] = hb16;
                hlob[(size_t)t * HID + tid] =
                    __float2bfloat16_rn(hv - __bfloat162float(hb16));
            }
            if (hlast && t == T_STEPS - 1) hlast[b * HID + tid] = hv;
        }
        bool pub = prog && ((t & 63) == 63);
        if (pub) __threadfence();          // all threads: release h writes
        __syncthreads();
        if (pub && tid == 0) atomicExch(prog + b, t + 1);
    }
}

// ---------------------------------------------------------------------------
// GEMM worker: pulls 128x128 tiles from an atomic pool (chunk-major order),
// paced by producer progress (prog). Publishes per-(b,chunk) counters.
// ---------------------------------------------------------------------------
__device__ void gemm_worker(const __nv_bfloat16* __restrict__ Whi,
                            const __nv_bfloat16* __restrict__ Wlo,
                            const float* __restrict__ bih, const float* __restrict__ bhh,
                            float* __restrict__ out,
                            const __nv_bfloat16* __restrict__ Hhi,
                            const __nv_bfloat16* __restrict__ Hlo,
                            int* __restrict__ prog, int* __restrict__ ctr,
                            int* __restrict__ chunkdone, char* gsm)
{
    const int tid = threadIdx.x;
    __shared__ int s_idx;
    const int NT = NCHUNK * BATCH * 4;   // 4096 tiles
    while (true) {
        if (tid == 0) s_idx = atomicAdd(ctr, 1);
        __syncthreads();
        int idx = s_idx;
        __syncthreads();
        if (idx >= NT) break;
        int chunk = idx >> 8;            // 0..15
        int b     = (idx >> 2) & 63;
        int cy    = idx & 3;
        if (tid == 0) {
            int need = (chunk + 1) * CHSTEP;
            int v;
            while (true) {
                asm volatile("ld.global.cg.u32 %0, [%1];" : "=r"(v) : "l"(prog + b));
                if (v >= need) break;
                __nanosleep(256);
            }
            __threadfence();
        }
        __syncthreads();
        gemm_tile(Hhi, Hlo, Whi, Wlo, bih, bhh, out,
                  b * T_STEPS + chunk * CHSTEP, cy * 128, gsm);
        __threadfence();                 // all threads: release tile stores
        __syncthreads();
        if (tid == 0) atomicAdd(chunkdone + b * NCHUNK + chunk, 1);
    }
}

// ---------------------------------------------------------------------------
// Mega kernel: all three rec layers pipelined in one launch.
//  blocks [0,64):    rec0 (publishes prog0) then rec2 (gated on chunk2)
//  blocks [64,128):  rec1 (gated on chunk1, publishes prog1), then gemm pools
//  blocks [128,148): gemm1 pool (h0->gx1), then gemm2 pool (h1->gx2)
// gx2 aliases gx0's buffer — safe by the causal chain
// prog1>=128(k+1) => rec1 consumed gx1[k] => gemm1[k] done =>
// prog0>=128(k+1) => rec0 finished reading gx0[k].
// ---------------------------------------------------------------------------
__global__ __launch_bounds__(256, 1) void mega_kernel(
    const float* __restrict__ whh,
    const float* __restrict__ bih, const float* __restrict__ bhh,
    float* __restrict__ gx0, float* __restrict__ gx1, float* __restrict__ gx2,
    int* __restrict__ syn)
{
    extern __shared__ char smraw[];
    const size_t WSZ = (size_t)GATES * HID;
    int* prog0  = syn;
    int* prog1  = syn + 64;
    int* ctrA   = syn + 128;
    int* ctrB   = syn + 129;
    int* chunk1 = syn + 130;
    int* chunk2 = chunk1 + BATCH * NCHUNK;

    const int bx = blockIdx.x;
    if (bx < BATCH) {
        rec_body(whh, gx0, g_h0hi, g_h0lo, nullptr, prog0, nullptr, bx, smraw);
        __syncthreads();
        rec_body(whh + 2 * WSZ, gx2, nullptr, nullptr, g_h2last,
                 nullptr, chunk2, bx, smraw);
    } else if (bx < 2 * BATCH) {
        rec_body(whh + WSZ, gx1, g_h1hi, g_h1lo, nullptr, prog1, chunk1,
                 bx - BATCH, smraw);
        __syncthreads();
        gemm_worker(g_whi + WSZ, g_wlo + WSZ, bih + GATES, bhh + GATES, gx1,
                    g_h0hi, g_h0lo, prog0, ctrA, chunk1, smraw);
        __syncthreads();
        gemm_worker(g_whi + 2 * WSZ, g_wlo + 2 * WSZ, bih + 2 * GATES,
                    bhh + 2 * GATES, gx2, g_h1hi, g_h1lo, prog1, ctrB, chunk2, smraw);
    } else {
        gemm_worker(g_whi + WSZ, g_wlo + WSZ, bih + GATES, bhh + GATES, gx1,
                    g_h0hi, g_h0lo, prog0, ctrA, chunk1, smraw);
        __syncthreads();
        gemm_worker(g_whi + 2 * WSZ, g_wlo + 2 * WSZ, bih + 2 * GATES,
                    bhh + 2 * GATES, gx2, g_h1hi, g_h1lo, prog1, ctrB, chunk2, smraw);
    }
}

// ---------------------------------------------------------------------------
// MLP head: 64 CTAs, one per batch row. h_last[128] -> 64 -> 32 -> 10.
// ---------------------------------------------------------------------------
__global__ __launch_bounds__(256) void mlp_kernel(
    const float* __restrict__ w1, const float* __restrict__ b1,
    const float* __restrict__ w2, const float* __restrict__ b2,
    const float* __restrict__ w3, const float* __restrict__ b3,
    float* __restrict__ out)
{
    __shared__ float hs[128];
    __shared__ float y1[64];
    __shared__ float y2[32];

    const int tid = threadIdx.x;
    const int b   = blockIdx.x;
    if (tid < 128) hs[tid] = g_h2last[b * HID + tid];
    __syncthreads();
    if (tid < 64) {
        float s = b1[tid];
        const float* wr = w1 + tid * 128;
#pragma unroll 16
        for (int k = 0; k < 128; k++) s = fmaf(hs[k], wr[k], s);
        y1[tid] = s;
    }
    __syncthreads();
    if (tid < 32) {
        float s = b2[tid];
        const float* wr = w2 + tid * 64;
#pragma unroll 16
        for (int k = 0; k < 64; k++) s = fmaf(y1[k], wr[k], s);
        y2[tid] = s;
    }
    __syncthreads();
    if (tid < 10) {
        float s = b3[tid];
        const float* wr = w3 + tid * 32;
#pragma unroll
        for (int k = 0; k < 32; k++) s = fmaf(y2[k], wr[k], s);
        out[b * 10 + tid] = s;
    }
}

// ---------------------------------------------------------------------------
extern "C" void kernel_launch(void* const* d_in, const int* in_sizes, int n_in,
                              void* d_out, int out_size)
{
    (void)in_sizes; (void)n_in; (void)out_size;
    const float* x   = (const float*)d_in[0];
    const float* wih = (const float*)d_in[1];
    const float* whh = (const float*)d_in[2];
    const float* bih = (const float*)d_in[3];
    const float* bhh = (const float*)d_in[4];
    const float* w1  = (const float*)d_in[5];
    const float* b1  = (const float*)d_in[6];
    const float* w2  = (const float*)d_in[7];
    const float* b2  = (const float*)d_in[8];
    const float* w3  = (const float*)d_in[9];
    const float* b3  = (const float*)d_in[10];

    void *pA = nullptr, *pB = nullptr, *pS = nullptr;
    void *pxh = nullptr, *pxl = nullptr, *pwh = nullptr, *pwl = nullptr;
    cudaGetSymbolAddress(&pA, g_gxA);
    cudaGetSymbolAddress(&pB, g_gxB);
    cudaGetSymbolAddress(&pS, g_syn);
    cudaGetSymbolAddress(&pxh, g_xhi);
    cudaGetSymbolAddress(&pxl, g_xlo);
    cudaGetSymbolAddress(&pwh, g_whi);
    cudaGetSymbolAddress(&pwl, g_wlo);
    float* bufA = (float*)pA;   // gx0, then gx2
    float* bufB = (float*)pB;   // gx1
    int*   syn  = (int*)pS;

    const int GEMM_SMEM = 4 * 128 * SR * 2 + 128 * 4;   // 139,776 B
    cudaFuncSetAttribute(gemm0_kernel, cudaFuncAttributeMaxDynamicSharedMemorySize, GEMM_SMEM);
    cudaFuncSetAttribute(mega_kernel,  cudaFuncAttributeMaxDynamicSharedMemorySize, GEMM_SMEM);

    cudaMemsetAsync(syn, 0, (130 + 2 * BATCH * NCHUNK) * sizeof(int));

    // Pre-split x and all wih layers into bf16 hi/lo
    const long XN4 = (long)BATCH * T_STEPS * HID / 4;          // 4,194,304
    const long WN4 = (long)3 * GATES * HID / 4;                // 49,152
    split_kernel<<<(unsigned)((XN4 + 255) / 256), 256>>>(
        x, (__nv_bfloat16*)pxh, (__nv_bfloat16*)pxl, XN4);
    split_kernel<<<(unsigned)((WN4 + 255) / 256), 256>>>(
        wih, (__nv_bfloat16*)pwh, (__nv_bfloat16*)pwl, WN4);

    // gx0 = x @ wih0^T + biases  -> bufA
    gemm0_kernel<<<dim3(BATCH * T_STEPS / 128, 4), 256, GEMM_SMEM>>>(bih, bhh);

    // All three rec layers + both inner GEMMs, pipelined per 128-step chunk.
    mega_kernel<<<NSM, 256, GEMM_SMEM>>>(whh, bih, bhh, bufA, bufB, bufA, syn);

    mlp_kernel<<<BATCH, 256>>>(w1, b1, w2, b2, w3, b3, (float*)d_out);
}